// round 14
// baseline (speedup 1.0000x reference)
#include <cuda_runtime.h>
#include <cuda_fp16.h>
#include <math.h>
#include <stdint.h>

#define CBATCH   4
#define CSEQ     2048
#define CDMODEL  1024
#define CDMAMBA  2048
#define CDSTATE  16
#define CNHEADS  32
#define CMROWS   (CBATCH * CSEQ)          // 8192
#define CNCHUNK  32
#define CLCHUNK  (CSEQ / CNCHUNK)         // 64
#define CHEADDIM (CDMAMBA / CNHEADS)      // 64

typedef unsigned short ushort_t;
typedef unsigned long long ull_t;

// ---------------- scratch ----------------
__device__ float g_Bn  [CMROWS * CDSTATE];
__device__ float g_Cn  [CMROWS * CDSTATE];
__device__ float g_hloc [CBATCH * CNCHUNK * CDSTATE * CDMAMBA];
__device__ float g_hinit[CBATCH * CNCHUNK * CDSTATE * CDMAMBA];
__device__ float g_S    [CBATCH * CNCHUNK * CDMAMBA];

__device__ ushort_t g_xn_h[CMROWS * CDMODEL];
__device__ ushort_t g_w1_h[CDMAMBA * CDMODEL];
__device__ ushort_t g_w2_h[CDMAMBA * CDMODEL];
__device__ ushort_t g_w3_h[CDMAMBA * CDMAMBA];
__device__ ushort_t g_x16 [CMROWS * CDMAMBA];
__device__ ushort_t g_dt16[CMROWS * CDMAMBA];
__device__ ushort_t g_y_h [CMROWS * CDMAMBA];

// ---------------- PTX helpers ----------------
__device__ __forceinline__ uint32_t smem_u32(const void* p) {
    uint32_t a;
    asm("{ .reg .u64 t; cvta.to.shared.u64 t, %1; cvt.u32.u64 %0, t; }" : "=r"(a) : "l"(p));
    return a;
}

#define CP_ASYNC16(dst, src) \
    asm volatile("cp.async.cg.shared.global [%0], [%1], 16;" :: "r"(dst), "l"(src))
#define CP_COMMIT() asm volatile("cp.async.commit_group;" ::: "memory")
#define CP_WAIT0() asm volatile("cp.async.wait_group 0;" ::: "memory")
#define CP_WAIT1() asm volatile("cp.async.wait_group 1;" ::: "memory")

#define LDSM4(r, addr) \
    asm volatile("ldmatrix.sync.aligned.m8n8.x4.shared.b16 {%0,%1,%2,%3}, [%4];" \
        : "=r"((r)[0]), "=r"((r)[1]), "=r"((r)[2]), "=r"((r)[3]) : "r"(addr))

#define MMA_F16(d, a, b0, b1) \
    asm volatile("mma.sync.aligned.m16n8k16.row.col.f32.f16.f16.f32 " \
        "{%0,%1,%2,%3}, {%4,%5,%6,%7}, {%8,%9}, {%0,%1,%2,%3};" \
        : "+f"((d)[0]), "+f"((d)[1]), "+f"((d)[2]), "+f"((d)[3]) \
        : "r"((a)[0]), "r"((a)[1]), "r"((a)[2]), "r"((a)[3]), "r"(b0), "r"(b1))

__device__ __forceinline__ uint32_t swz(uint32_t off) {
    return off ^ ((off >> 3) & 0x70);
}

__device__ __forceinline__ ull_t pk2(float lo, float hi) {
    ull_t r; asm("mov.b64 %0, {%1, %2};" : "=l"(r) : "f"(lo), "f"(hi)); return r;
}
__device__ __forceinline__ void upk2(ull_t v, float& lo, float& hi) {
    asm("mov.b64 {%0, %1}, %2;" : "=f"(lo), "=f"(hi) : "l"(v));
}
__device__ __forceinline__ ull_t mul2(ull_t a, ull_t b) {
    ull_t r; asm("mul.rn.f32x2 %0, %1, %2;" : "=l"(r) : "l"(a), "l"(b)); return r;
}
__device__ __forceinline__ ull_t fma2(ull_t a, ull_t b, ull_t c) {
    ull_t r; asm("fma.rn.f32x2 %0, %1, %2, %3;" : "=l"(r) : "l"(a), "l"(b), "l"(c)); return r;
}

// ---------------- conversions ----------------
__device__ __forceinline__ void conv_one(const float* __restrict__ in,
                                         ushort_t* __restrict__ hi, int i) {
    float4 v = reinterpret_cast<const float4*>(in)[i];
    ushort4 h;
    h.x = __half_as_ushort(__float2half(v.x));
    h.y = __half_as_ushort(__float2half(v.y));
    h.z = __half_as_ushort(__float2half(v.z));
    h.w = __half_as_ushort(__float2half(v.w));
    reinterpret_cast<ushort4*>(hi)[i] = h;
}

__global__ __launch_bounds__(256) void conv3(const float* __restrict__ xn, ushort_t* xh,
                                             const float* __restrict__ w1, ushort_t* w1h,
                                             const float* __restrict__ w2, ushort_t* w2h) {
    const int NA = (CMROWS * CDMODEL) / 4;
    const int NB = (CDMAMBA * CDMODEL) / 4;
    int id = blockIdx.x * 256 + threadIdx.x;
    if (id < NA)               conv_one(xn, xh, id);
    else if (id < NA + NB)     conv_one(w1, w1h, id - NA);
    else                       conv_one(w2, w2h, id - NA - NB);
}

__device__ __forceinline__ float dt_transform(float v, float b) {
    v += b;
    v = fminf(fmaxf(v, -10.0f), 5.0f);
    v = log1pf(expf(v));
    return fminf(fmaxf(v, 1e-4f), 0.1f);
}

// ---------------- GEMM building blocks (champion R8 geometry) ----------------
#define TILE_B   16384
#define STAGE_B  32768
#define SM_TOTAL (3 * STAGE_B)

__device__ __forceinline__ void stage_load(
    const ushort_t* __restrict__ Ah, const ushort_t* __restrict__ Wh,
    uint32_t sbase, int m0, int n0, int kc, int K, int tid) {
#pragma unroll
    for (int tile = 0; tile < 2; tile++) {
        const ushort_t* g = (tile == 0) ? Ah : Wh;
        int row0 = (tile == 0) ? m0 : n0;
#pragma unroll
        for (int j = 0; j < 4; j++) {
            int idx = tid + j * 256;
            int row = idx >> 3, seg = idx & 7;
            const ushort_t* src = g + (size_t)(row0 + row) * K + kc + seg * 8;
            uint32_t dst = sbase + tile * TILE_B + swz((uint32_t)(row * 128 + seg * 16));
            CP_ASYNC16(dst, src);
        }
    }
}

__device__ __forceinline__ void ldsm_frags(uint32_t aA, uint32_t aW,
                                           int arow, int akb, int brow, int bkb,
                                           int kb, uint32_t ah[2][4], uint32_t bh[4][4]) {
#pragma unroll
    for (int mi = 0; mi < 2; mi++) {
        uint32_t off = swz((uint32_t)((arow + mi * 16) * 128 + akb + kb));
        LDSM4(ah[mi], aA + off);
    }
#pragma unroll
    for (int ni = 0; ni < 4; ni++) {
        uint32_t off = swz((uint32_t)((brow + ni * 16) * 128 + bkb + kb));
        LDSM4(bh[ni], aW + off);
    }
}

__device__ __forceinline__ void stage_compute(uint32_t sbase, int wm, int wn,
                                              int lane, float acc[2][8][4]) {
    const uint32_t aA = sbase;
    const uint32_t aW = sbase + TILE_B;
    const int arow = wm + (lane & 15);
    const int akb  = (lane >> 4) * 16;
    const int brow = wn + ((lane >> 4) << 3) + (lane & 7);
    const int bkb  = ((lane >> 3) & 1) * 16;

    uint32_t ah[2][2][4], bh[2][4][4];
    ldsm_frags(aA, aW, arow, akb, brow, bkb, 0, ah[0], bh[0]);

#pragma unroll
    for (int ks = 0; ks < 4; ks++) {
        const int cur = ks & 1;
        if (ks < 3)
            ldsm_frags(aA, aW, arow, akb, brow, bkb, (ks + 1) * 32,
                       ah[cur ^ 1], bh[cur ^ 1]);
#pragma unroll
        for (int mi = 0; mi < 2; mi++) {
#pragma unroll
            for (int ni = 0; ni < 4; ni++) {
                MMA_F16(acc[mi][2 * ni + 0], ah[cur][mi], bh[cur][ni][0], bh[cur][ni][1]);
                MMA_F16(acc[mi][2 * ni + 1], ah[cur][mi], bh[cur][ni][2], bh[cur][ni][3]);
            }
        }
    }
}

template <bool OUT16>
__device__ __forceinline__ void gemm_body(
    char* smem, const ushort_t* __restrict__ Ah, const ushort_t* __restrict__ Wh,
    bool second, const float* __restrict__ bias,
    ushort_t* __restrict__ C1h, ushort_t* __restrict__ C2h, float* __restrict__ Cf,
    int m0, int n0, int N, int K) {
    const uint32_t sb = smem_u32(smem);
    const int tid = threadIdx.x, lane = tid & 31, w = tid >> 5;
    const int wm = (w & 3) * 32, wn = (w >> 2) * 64;
    const int NC = K >> 6;

    float acc[2][8][4];
#pragma unroll
    for (int i = 0; i < 2; i++)
#pragma unroll
        for (int j = 0; j < 8; j++)
#pragma unroll
            for (int q = 0; q < 4; q++) acc[i][j][q] = 0.0f;

    stage_load(Ah, Wh, sb + 0 * STAGE_B, m0, n0, 0, K, tid);  CP_COMMIT();
    stage_load(Ah, Wh, sb + 1 * STAGE_B, m0, n0, 64, K, tid); CP_COMMIT();

    int sc = 0, sl = 2;
    for (int c = 0; c < NC; c++) {
        if (c + 1 < NC) { CP_WAIT1(); } else { CP_WAIT0(); }
        __syncthreads();
        if (c + 2 < NC) {
            stage_load(Ah, Wh, sb + sl * STAGE_B, m0, n0, (c + 2) * 64, K, tid);
            CP_COMMIT();
            sl = (sl == 2) ? 0 : sl + 1;
        }
        stage_compute(sb + sc * STAGE_B, wm, wn, lane, acc);
        sc = (sc == 2) ? 0 : sc + 1;
    }

    const int gm = m0 + wm, gn = n0 + wn;
    const int r = lane >> 2, cp = (lane & 3) * 2;
#pragma unroll
    for (int mi = 0; mi < 2; mi++) {
#pragma unroll
        for (int nj = 0; nj < 8; nj++) {
            int row = gm + mi * 16 + r;
            int col = gn + nj * 8 + cp;
            float v0 = acc[mi][nj][0], v1 = acc[mi][nj][1];
            float v2 = acc[mi][nj][2], v3 = acc[mi][nj][3];
            if (OUT16) {
                if (second) {
                    float2 bb = *reinterpret_cast<const float2*>(&bias[col]);
                    v0 = dt_transform(v0, bb.x);
                    v1 = dt_transform(v1, bb.y);
                    v2 = dt_transform(v2, bb.x);
                    v3 = dt_transform(v3, bb.y);
                }
                ushort_t* C = second ? C2h : C1h;
                __half2 h01 = __halves2half2(__float2half(v0), __float2half(v1));
                __half2 h23 = __halves2half2(__float2half(v2), __float2half(v3));
                *reinterpret_cast<__half2*>(&C[(size_t)row * N + col]) = h01;
                *reinterpret_cast<__half2*>(&C[(size_t)(row + 8) * N + col]) = h23;
            } else {
                *reinterpret_cast<float2*>(&Cf[(size_t)row * N + col]) = make_float2(v0, v1);
                *reinterpret_cast<float2*>(&Cf[(size_t)(row + 8) * N + col]) = make_float2(v2, v3);
            }
        }
    }
}

__device__ __forceinline__ void bc_body(char* smem, int bid,
                                        const float* __restrict__ X,
                                        const float* __restrict__ WB,
                                        const float* __restrict__ WC) {
    float (*Xs)[65] = reinterpret_cast<float (*)[65]>(smem);
    float (*Ws)[65] = reinterpret_cast<float (*)[65]>(smem + 32 * 65 * sizeof(float));
    const int tid = threadIdx.x;
    const int tx = tid & 31;
    const int ty = tid >> 5;
    const int m0 = bid * 32;

    float acc[4];
#pragma unroll
    for (int i = 0; i < 4; i++) acc[i] = 0.0f;

    for (int kt = 0; kt < CDMODEL; kt += 64) {
#pragma unroll
        for (int j = 0; j < 2; j++) {
            int q = tid + j * 256;
            int row = q >> 4;
            int c4 = (q & 15) * 4;
            float4 v = *reinterpret_cast<const float4*>(&X[(size_t)(m0 + row) * CDMODEL + kt + c4]);
            Xs[row][c4 + 0] = v.x; Xs[row][c4 + 1] = v.y;
            Xs[row][c4 + 2] = v.z; Xs[row][c4 + 3] = v.w;
        }
#pragma unroll
        for (int j = 0; j < 2; j++) {
            int q = tid + j * 256;
            int row = q >> 4;
            int c4 = (q & 15) * 4;
            const float* Wsrc = (row < 16) ? &WB[(size_t)row * CDMODEL]
                                           : &WC[(size_t)(row - 16) * CDMODEL];
            float4 v = *reinterpret_cast<const float4*>(&Wsrc[kt + c4]);
            Ws[row][c4 + 0] = v.x; Ws[row][c4 + 1] = v.y;
            Ws[row][c4 + 2] = v.z; Ws[row][c4 + 3] = v.w;
        }
        __syncthreads();
#pragma unroll 8
        for (int k = 0; k < 64; k++) {
            float wv = Ws[tx][k];
#pragma unroll
            for (int i = 0; i < 4; i++)
                acc[i] = fmaf(Xs[ty * 4 + i][k], wv, acc[i]);
        }
        __syncthreads();
    }

#pragma unroll
    for (int i = 0; i < 4; i++) {
        float v = acc[i];
        float ss = v * v;
#pragma unroll
        for (int off = 8; off >= 1; off >>= 1)
            ss += __shfl_xor_sync(0xffffffffu, ss, off);
        float sc = 1.0f / fmaxf(sqrtf(ss), 1.0f);
        v *= sc;
        int m = m0 + ty * 4 + i;
        if (tx < 16) g_Bn[(size_t)m * 16 + tx] = v;
        else         g_Cn[(size_t)m * 16 + (tx - 16)] = v;
    }
}

__global__ __launch_bounds__(256, 2) void fused_front(
    const ushort_t* __restrict__ Ah,
    const ushort_t* __restrict__ W1, const ushort_t* __restrict__ W2,
    const float* __restrict__ bias,
    ushort_t* __restrict__ C1h, ushort_t* __restrict__ C2h,
    const float* __restrict__ X, const float* __restrict__ WB, const float* __restrict__ WC,
    const float* __restrict__ w3src, ushort_t* __restrict__ w3h) {
    extern __shared__ __align__(1024) char smem[];
    const int bx = blockIdx.x, by = blockIdx.y;

    if (bx < 32) {
        const bool second = (bx >= 16);
        const int n0 = (second ? bx - 16 : bx) * 128;
        const int m0 = by * 128;
        gemm_body<true>(smem, Ah, second ? W2 : W1, second, bias,
                        C1h, C2h, nullptr, m0, n0, CDMAMBA, CDMODEL);
    } else if (bx < 36) {
        bc_body(smem, (bx - 32) * 64 + by, X, WB, WC);
    } else {
        int id = ((bx - 36) * 64 + by) * 256 + threadIdx.x;
        conv_one(w3src, w3h, id);
    }
}

__global__ __launch_bounds__(256, 2) void gemm_out(
    const ushort_t* __restrict__ Ah, const ushort_t* __restrict__ Wh,
    float* __restrict__ Cf, int N, int K) {
    extern __shared__ __align__(1024) char smem[];
    gemm_body<false>(smem, Ah, Wh, false, nullptr, nullptr, nullptr, Cf,
                     blockIdx.y * 128, blockIdx.x * 128, N, K);
}

// ---------------- scan helpers ----------------
__device__ __forceinline__ bool check_fastA(const float* __restrict__ A_log, int d0) {
    int head = d0 / CHEADDIM;
    bool fast = true;
#pragma unroll
    for (int n = 0; n < 16; n++) {
        float a = expf(A_log[head * 16 + n]);
        if (fabsf(a - (float)(n + 1)) > 1e-3f * (float)(n + 1)) fast = false;
    }
    return fast;
}

__device__ __forceinline__ void load_Av(const float* __restrict__ A_log, int d, float* Av) {
    int head = d / CHEADDIM;
#pragma unroll
    for (int n = 0; n < 16; n++) Av[n] = expf(A_log[head * 16 + n]);
}

__device__ __forceinline__ void load16p(const float* p, ull_t* v) {
    const float4* q = reinterpret_cast<const float4*>(p);
    float4 a = q[0], b = q[1], c = q[2], d = q[3];
    v[0] = pk2(a.x, a.y); v[1] = pk2(a.z, a.w);
    v[2] = pk2(b.x, b.y); v[3] = pk2(b.z, b.w);
    v[4] = pk2(c.x, c.y); v[5] = pk2(c.z, c.w);
    v[6] = pk2(d.x, d.y); v[7] = pk2(d.z, d.w);
}

__device__ __forceinline__ void scan_step(ull_t* hp, const ull_t* Bp, float r, float dtx) {
    float r2 = r * r;
    ull_t p = pk2(r, r2);
    ull_t r22 = pk2(r2, r2);
    ull_t dtx2 = pk2(dtx, dtx);
#pragma unroll
    for (int k = 0; k < 8; k++) {
        if (k > 0) p = mul2(p, r22);
        hp[k] = fma2(p, hp[k], mul2(Bp[k], dtx2));
    }
}

__device__ __forceinline__ void scan_step_gen(ull_t* hp, const ull_t* Bp, const ull_t* Avp,
                                              float dt, float dtx) {
    ull_t dtx2 = pk2(dtx, dtx);
#pragma unroll
    for (int k = 0; k < 8; k++) {
        float a0, a1;
        upk2(Avp[k], a0, a1);
        ull_t dec = pk2(__expf(-dt * a0), __expf(-dt * a1));
        hp[k] = fma2(dec, hp[k], mul2(Bp[k], dtx2));
    }
}

// correction dot: sum_n hinit_n * r^(n+1) * C_n  (power chain in packed pairs)
__device__ __forceinline__ float corr_dot(const ull_t* hi, const ull_t* Cp, float r) {
    float r2 = r * r;
    ull_t p = pk2(r, r2);
    ull_t r22 = pk2(r2, r2);
    ull_t acc = pk2(0.0f, 0.0f);
#pragma unroll
    for (int k = 0; k < 8; k++) {
        if (k > 0) p = mul2(p, r22);
        acc = fma2(mul2(hi[k], p), Cp[k], acc);
    }
    float a, b;
    upk2(acc, a, b);
    return a + b;
}

__device__ __forceinline__ float corr_dot_gen(const ull_t* hi, const ull_t* Cp,
                                              const ull_t* Avp, float P) {
    ull_t acc = pk2(0.0f, 0.0f);
#pragma unroll
    for (int k = 0; k < 8; k++) {
        float a0, a1;
        upk2(Avp[k], a0, a1);
        ull_t dec = pk2(__expf(-P * a0), __expf(-P * a1));
        acc = fma2(mul2(hi[k], dec), Cp[k], acc);
    }
    float a, b;
    upk2(acc, a, b);
    return a + b;
}

// ---------------- scan pass 1: full local replay (h from 0), emits y_local, hloc, S ----
__global__ __launch_bounds__(256) void scan_pass1(const float* __restrict__ A_log,
                                                  const float* __restrict__ Dvec) {
    int i = blockIdx.x * 256 + threadIdx.x;
    int d0 = 2 * i;
    int c = blockIdx.y;
    int b = blockIdx.z;

    bool fastA = check_fastA(A_log, d0);
    ull_t Avp[8];
    if (!fastA) {
        float Av[16];
        load_Av(A_log, d0, Av);
#pragma unroll
        for (int k = 0; k < 8; k++) Avp[k] = pk2(Av[2 * k], Av[2 * k + 1]);
    }
    float2 Dd = *reinterpret_cast<const float2*>(&Dvec[d0]);

    ull_t h0[8], h1[8];
    const ull_t z = pk2(0.0f, 0.0f);
#pragma unroll
    for (int k = 0; k < 8; k++) { h0[k] = z; h1[k] = z; }
    float S0 = 0.0f, S1 = 0.0f;

    int row0 = b * CSEQ + c * CLCHUNK;
    for (int t = 0; t < CLCHUNK; t++) {
        size_t ro = (size_t)(row0 + t) * CDMAMBA + d0;
        __half2 dtp = *reinterpret_cast<const __half2*>(&g_dt16[ro]);
        __half2 xp  = *reinterpret_cast<const __half2*>(&g_x16[ro]);
        float dt0 = __low2float(dtp), dt1 = __high2float(dtp);
        float x0 = __low2float(xp),   x1 = __high2float(xp);
        ull_t Bp[8], Cp[8];
        load16p(g_Bn + (size_t)(row0 + t) * 16, Bp);
        load16p(g_Cn + (size_t)(row0 + t) * 16, Cp);
        S0 += dt0; S1 += dt1;
        if (fastA) {
            scan_step(h0, Bp, __expf(-dt0), dt0 * x0);
            scan_step(h1, Bp, __expf(-dt1), dt1 * x1);
        } else {
            scan_step_gen(h0, Bp, Avp, dt0, dt0 * x0);
            scan_step_gen(h1, Bp, Avp, dt1, dt1 * x1);
        }
        ull_t y0p = z, y1p = z;
#pragma unroll
        for (int k = 0; k < 8; k++) {
            y0p = fma2(h0[k], Cp[k], y0p);
            y1p = fma2(h1[k], Cp[k], y1p);
        }
        float ya, yb, yc, yd;
        upk2(y0p, ya, yb);
        upk2(y1p, yc, yd);
        __half2 out = __halves2half2(__float2half(fmaf(x0, Dd.x, ya + yb)),
                                     __float2half(fmaf(x1, Dd.y, yc + yd)));
        *reinterpret_cast<__half2*>(&g_y_h[ro]) = out;
    }
    size_t base = ((size_t)(b * CNCHUNK + c) * 16) * CDMAMBA + d0;
#pragma unroll
    for (int k = 0; k < 8; k++) {
        float a0, a1, b0, b1;
        upk2(h0[k], a0, a1);
        upk2(h1[k], b0, b1);
        *reinterpret_cast<float2*>(&g_hloc[base + (size_t)(2 * k) * CDMAMBA]) = make_float2(a0, b0);
        *reinterpret_cast<float2*>(&g_hloc[base + (size_t)(2 * k + 1) * CDMAMBA]) = make_float2(a1, b1);
    }
    *reinterpret_cast<float2*>(&g_S[(size_t)(b * CNCHUNK + c) * CDMAMBA + d0]) = make_float2(S0, S1);
}

// ---------------- scan pass 2: one (b, n, d) chain per thread ----------------
__global__ __launch_bounds__(256) void scan_pass2(const float* __restrict__ A_log) {
    int idx = blockIdx.x * 256 + threadIdx.x;
    int d = idx % CDMAMBA;
    int bn = idx / CDMAMBA;
    int n = bn & 15;
    int b = bn >> 4;

    int head = d / CHEADDIM;
    float An = expf(A_log[head * 16 + n]);

    float h = 0.0f;
    for (int c = 0; c < CNCHUNK; c++) {
        size_t sidx = (size_t)(b * CNCHUNK + c) * CDMAMBA + d;
        size_t hidx = ((size_t)(b * CNCHUNK + c) * 16 + n) * CDMAMBA + d;
        g_hinit[hidx] = h;
        float S = g_S[sidx];
        h = fmaf(__expf(-S * An), h, g_hloc[hidx]);
    }
}

// ---------------- scan fix: y += sum_n C_n(t) h_init_n exp(-A_n P_t) ----------------
__global__ __launch_bounds__(256) void scan_fix(const float* __restrict__ A_log) {
    int c = blockIdx.y;
    if (c == 0) return;                         // h_init == 0 for first chunk
    int i = blockIdx.x * 256 + threadIdx.x;
    int d0 = 2 * i;
    int b = blockIdx.z;

    bool fastA = check_fastA(A_log, d0);
    ull_t Avp[8];
    if (!fastA) {
        float Av[16];
        load_Av(A_log, d0, Av);
#pragma unroll
        for (int k = 0; k < 8; k++) Avp[k] = pk2(Av[2 * k], Av[2 * k + 1]);
    }

    ull_t hi0[8], hi1[8];
    size_t base = ((size_t)(b * CNCHUNK + c) * 16) * CDMAMBA + d0;
#pragma unroll
    for (int k = 0; k < 8; k++) {
        float2 va = *reinterpret_cast<const float2*>(&g_hinit[base + (size_t)(2 * k) * CDMAMBA]);
        float2 vb = *reinterpret_cast<const float2*>(&g_hinit[base + (size_t)(2 * k + 1) * CDMAMBA]);
        hi0[k] = pk2(va.x, vb.x);
        hi1[k] = pk2(va.y, vb.y);
    }

    float P0 = 0.0f, P1 = 0.0f;
    int row0 = b * CSEQ + c * CLCHUNK;
    for (int t = 0; t < CLCHUNK; t++) {
        size_t ro = (size_t)(row0 + t) * CDMAMBA + d0;
        __half2 dtp = *reinterpret_cast<const __half2*>(&g_dt16[ro]);
        P0 += __low2float(dtp);
        P1 += __high2float(dtp);
        ull_t Cp[8];
        load16p(g_Cn + (size_t)(row0 + t) * 16, Cp);
        float corr0, corr1;
        if (fastA) {
            corr0 = corr_dot(hi0, Cp, __expf(-P0));
            corr1 = corr_dot(hi1, Cp, __expf(-P1));
        } else {
            corr0 = corr_dot_gen(hi0, Cp, Avp, P0);
            corr1 = corr_dot_gen(hi1, Cp, Avp, P1);
        }
        __half2 yv = *reinterpret_cast<const __half2*>(&g_y_h[ro]);
        __half2 out = __halves2half2(__float2half(__low2float(yv) + corr0),
                                     __float2half(__high2float(yv) + corr1));
        *reinterpret_cast<__half2*>(&g_y_h[ro]) = out;
    }
}

// ---------------- launch ----------------
extern "C" void kernel_launch(void* const* d_in, const int* in_sizes, int n_in,
                              void* d_out, int out_size) {
    (void)in_sizes; (void)n_in; (void)out_size;
    const float* x_norm     = (const float*)d_in[0];
    const float* x_proj_w   = (const float*)d_in[1];
    const float* dt_proj_w  = (const float*)d_in[2];
    const float* dt_proj_b  = (const float*)d_in[3];
    const float* B_proj_w   = (const float*)d_in[4];
    const float* C_proj_w   = (const float*)d_in[5];
    const float* A_log      = (const float*)d_in[6];
    const float* Dvec       = (const float*)d_in[7];
    const float* out_proj_w = (const float*)d_in[8];
    float* out = (float*)d_out;

    void *p_xnh, *p_w1h, *p_w2h, *p_w3h, *p_yh, *p_x16, *p_dt16;
    cudaGetSymbolAddress(&p_xnh, g_xn_h);
    cudaGetSymbolAddress(&p_w1h, g_w1_h);
    cudaGetSymbolAddress(&p_w2h, g_w2_h);
    cudaGetSymbolAddress(&p_w3h, g_w3_h);
    cudaGetSymbolAddress(&p_yh, g_y_h);
    cudaGetSymbolAddress(&p_x16, g_x16);
    cudaGetSymbolAddress(&p_dt16, g_dt16);

    cudaFuncSetAttribute(fused_front, cudaFuncAttributeMaxDynamicSharedMemorySize, SM_TOTAL);
    cudaFuncSetAttribute(gemm_out, cudaFuncAttributeMaxDynamicSharedMemorySize, SM_TOTAL);

    // input conversions: xn, w1, w2
    {
        int total = (CMROWS * CDMODEL + 2 * CDMAMBA * CDMODEL) / 4;
        conv3<<<total / 256, 256>>>(x_norm, (ushort_t*)p_xnh,
                                    x_proj_w, (ushort_t*)p_w1h,
                                    dt_proj_w, (ushort_t*)p_w2h);
    }

    // fused front: GEMM1+2 + bc + conv_w3
    {
        dim3 grid(100, 64);
        fused_front<<<grid, 256, SM_TOTAL>>>(
            (const ushort_t*)p_xnh,
            (const ushort_t*)p_w1h, (const ushort_t*)p_w2h, dt_proj_b,
            (ushort_t*)p_x16, (ushort_t*)p_dt16,
            x_norm, B_proj_w, C_proj_w,
            out_proj_w, (ushort_t*)p_w3h);
    }

    // scan: full local replay -> chunk combine -> light correction
    dim3 scan_grid((CDMAMBA / 2) / 256, CNCHUNK, CBATCH);
    scan_pass1<<<scan_grid, 256>>>(A_log, Dvec);
    scan_pass2<<<(CBATCH * 16 * CDMAMBA) / 256, 256>>>(A_log);
    scan_fix<<<scan_grid, 256>>>(A_log);

    // out = y @ out_proj_w^T (fp32)
    {
        dim3 grid(CDMAMBA / 128, CMROWS / 128);
        gemm_out<<<grid, 256, SM_TOTAL>>>(
            (const ushort_t*)p_yh, (const ushort_t*)p_w3h, out, CDMAMBA, CDMAMBA);
    }
}

// round 15
// speedup vs baseline: 1.0006x; 1.0006x over previous
#include <cuda_runtime.h>
#include <cuda_fp16.h>
#include <math.h>
#include <stdint.h>

#define CBATCH   4
#define CSEQ     2048
#define CDMODEL  1024
#define CDMAMBA  2048
#define CDSTATE  16
#define CNHEADS  32
#define CMROWS   (CBATCH * CSEQ)          // 8192
#define CNCHUNK  32
#define CLCHUNK  (CSEQ / CNCHUNK)         // 64
#define CHEADDIM (CDMAMBA / CNHEADS)      // 64

typedef unsigned short ushort_t;
typedef unsigned long long ull_t;

// ---------------- scratch ----------------
__device__ float g_Bn  [CMROWS * CDSTATE];
__device__ float g_Cn  [CMROWS * CDSTATE];
__device__ float g_hloc [CBATCH * CNCHUNK * CDSTATE * CDMAMBA];
__device__ float g_hinit[CBATCH * CNCHUNK * CDSTATE * CDMAMBA];
__device__ float g_S    [CBATCH * CNCHUNK * CDMAMBA];

__device__ ushort_t g_xn_h[CMROWS * CDMODEL];
__device__ ushort_t g_w1_h[CDMAMBA * CDMODEL];
__device__ ushort_t g_w2_h[CDMAMBA * CDMODEL];
__device__ ushort_t g_w3_h[CDMAMBA * CDMAMBA];
__device__ ushort_t g_x16 [CMROWS * CDMAMBA];
__device__ ushort_t g_dt16[CMROWS * CDMAMBA];
__device__ ushort_t g_y_h [CMROWS * CDMAMBA];

// ---------------- PTX helpers ----------------
__device__ __forceinline__ uint32_t smem_u32(const void* p) {
    uint32_t a;
    asm("{ .reg .u64 t; cvta.to.shared.u64 t, %1; cvt.u32.u64 %0, t; }" : "=r"(a) : "l"(p));
    return a;
}

#define CP_ASYNC16(dst, src) \
    asm volatile("cp.async.cg.shared.global [%0], [%1], 16;" :: "r"(dst), "l"(src))
#define CP_COMMIT() asm volatile("cp.async.commit_group;" ::: "memory")
#define CP_WAIT0() asm volatile("cp.async.wait_group 0;" ::: "memory")
#define CP_WAIT1() asm volatile("cp.async.wait_group 1;" ::: "memory")

#define LDSM4(r, addr) \
    asm volatile("ldmatrix.sync.aligned.m8n8.x4.shared.b16 {%0,%1,%2,%3}, [%4];" \
        : "=r"((r)[0]), "=r"((r)[1]), "=r"((r)[2]), "=r"((r)[3]) : "r"(addr))

#define MMA_F16(d, a, b0, b1) \
    asm volatile("mma.sync.aligned.m16n8k16.row.col.f32.f16.f16.f32 " \
        "{%0,%1,%2,%3}, {%4,%5,%6,%7}, {%8,%9}, {%0,%1,%2,%3};" \
        : "+f"((d)[0]), "+f"((d)[1]), "+f"((d)[2]), "+f"((d)[3]) \
        : "r"((a)[0]), "r"((a)[1]), "r"((a)[2]), "r"((a)[3]), "r"(b0), "r"(b1))

__device__ __forceinline__ uint32_t swz(uint32_t off) {
    return off ^ ((off >> 3) & 0x70);
}

__device__ __forceinline__ ull_t pk2(float lo, float hi) {
    ull_t r; asm("mov.b64 %0, {%1, %2};" : "=l"(r) : "f"(lo), "f"(hi)); return r;
}
__device__ __forceinline__ void upk2(ull_t v, float& lo, float& hi) {
    asm("mov.b64 {%0, %1}, %2;" : "=f"(lo), "=f"(hi) : "l"(v));
}
__device__ __forceinline__ ull_t mul2(ull_t a, ull_t b) {
    ull_t r; asm("mul.rn.f32x2 %0, %1, %2;" : "=l"(r) : "l"(a), "l"(b)); return r;
}
__device__ __forceinline__ ull_t fma2(ull_t a, ull_t b, ull_t c) {
    ull_t r; asm("fma.rn.f32x2 %0, %1, %2, %3;" : "=l"(r) : "l"(a), "l"(b), "l"(c)); return r;
}

// ---------------- conversions ----------------
__device__ __forceinline__ void conv_one(const float* __restrict__ in,
                                         ushort_t* __restrict__ hi, int i) {
    float4 v = reinterpret_cast<const float4*>(in)[i];
    ushort4 h;
    h.x = __half_as_ushort(__float2half(v.x));
    h.y = __half_as_ushort(__float2half(v.y));
    h.z = __half_as_ushort(__float2half(v.z));
    h.w = __half_as_ushort(__float2half(v.w));
    reinterpret_cast<ushort4*>(hi)[i] = h;
}

__global__ __launch_bounds__(256) void conv3(const float* __restrict__ xn, ushort_t* xh,
                                             const float* __restrict__ w1, ushort_t* w1h,
                                             const float* __restrict__ w2, ushort_t* w2h) {
    const int NA = (CMROWS * CDMODEL) / 4;
    const int NB = (CDMAMBA * CDMODEL) / 4;
    int id = blockIdx.x * 256 + threadIdx.x;
    if (id < NA)               conv_one(xn, xh, id);
    else if (id < NA + NB)     conv_one(w1, w1h, id - NA);
    else                       conv_one(w2, w2h, id - NA - NB);
}

__device__ __forceinline__ float dt_transform(float v, float b) {
    v += b;
    v = fminf(fmaxf(v, -10.0f), 5.0f);
    v = log1pf(expf(v));
    return fminf(fmaxf(v, 1e-4f), 0.1f);
}

// ---------------- GEMM building blocks (champion R8 geometry) ----------------
#define TILE_B   16384
#define STAGE_B  32768
#define SM_TOTAL (3 * STAGE_B)

__device__ __forceinline__ void stage_load(
    const ushort_t* __restrict__ Ah, const ushort_t* __restrict__ Wh,
    uint32_t sbase, int m0, int n0, int kc, int K, int tid) {
#pragma unroll
    for (int tile = 0; tile < 2; tile++) {
        const ushort_t* g = (tile == 0) ? Ah : Wh;
        int row0 = (tile == 0) ? m0 : n0;
#pragma unroll
        for (int j = 0; j < 4; j++) {
            int idx = tid + j * 256;
            int row = idx >> 3, seg = idx & 7;
            const ushort_t* src = g + (size_t)(row0 + row) * K + kc + seg * 8;
            uint32_t dst = sbase + tile * TILE_B + swz((uint32_t)(row * 128 + seg * 16));
            CP_ASYNC16(dst, src);
        }
    }
}

__device__ __forceinline__ void ldsm_frags(uint32_t aA, uint32_t aW,
                                           int arow, int akb, int brow, int bkb,
                                           int kb, uint32_t ah[2][4], uint32_t bh[4][4]) {
#pragma unroll
    for (int mi = 0; mi < 2; mi++) {
        uint32_t off = swz((uint32_t)((arow + mi * 16) * 128 + akb + kb));
        LDSM4(ah[mi], aA + off);
    }
#pragma unroll
    for (int ni = 0; ni < 4; ni++) {
        uint32_t off = swz((uint32_t)((brow + ni * 16) * 128 + bkb + kb));
        LDSM4(bh[ni], aW + off);
    }
}

__device__ __forceinline__ void stage_compute(uint32_t sbase, int wm, int wn,
                                              int lane, float acc[2][8][4]) {
    const uint32_t aA = sbase;
    const uint32_t aW = sbase + TILE_B;
    const int arow = wm + (lane & 15);
    const int akb  = (lane >> 4) * 16;
    const int brow = wn + ((lane >> 4) << 3) + (lane & 7);
    const int bkb  = ((lane >> 3) & 1) * 16;

    uint32_t ah[2][2][4], bh[2][4][4];
    ldsm_frags(aA, aW, arow, akb, brow, bkb, 0, ah[0], bh[0]);

#pragma unroll
    for (int ks = 0; ks < 4; ks++) {
        const int cur = ks & 1;
        if (ks < 3)
            ldsm_frags(aA, aW, arow, akb, brow, bkb, (ks + 1) * 32,
                       ah[cur ^ 1], bh[cur ^ 1]);
#pragma unroll
        for (int mi = 0; mi < 2; mi++) {
#pragma unroll
            for (int ni = 0; ni < 4; ni++) {
                MMA_F16(acc[mi][2 * ni + 0], ah[cur][mi], bh[cur][ni][0], bh[cur][ni][1]);
                MMA_F16(acc[mi][2 * ni + 1], ah[cur][mi], bh[cur][ni][2], bh[cur][ni][3]);
            }
        }
    }
}

template <bool OUT16>
__device__ __forceinline__ void gemm_body(
    char* smem, const ushort_t* __restrict__ Ah, const ushort_t* __restrict__ Wh,
    bool second, const float* __restrict__ bias,
    ushort_t* __restrict__ C1h, ushort_t* __restrict__ C2h, float* __restrict__ Cf,
    int m0, int n0, int N, int K) {
    const uint32_t sb = smem_u32(smem);
    const int tid = threadIdx.x, lane = tid & 31, w = tid >> 5;
    const int wm = (w & 3) * 32, wn = (w >> 2) * 64;
    const int NC = K >> 6;

    float acc[2][8][4];
#pragma unroll
    for (int i = 0; i < 2; i++)
#pragma unroll
        for (int j = 0; j < 8; j++)
#pragma unroll
            for (int q = 0; q < 4; q++) acc[i][j][q] = 0.0f;

    stage_load(Ah, Wh, sb + 0 * STAGE_B, m0, n0, 0, K, tid);  CP_COMMIT();
    stage_load(Ah, Wh, sb + 1 * STAGE_B, m0, n0, 64, K, tid); CP_COMMIT();

    int sc = 0, sl = 2;
    for (int c = 0; c < NC; c++) {
        if (c + 1 < NC) { CP_WAIT1(); } else { CP_WAIT0(); }
        __syncthreads();
        if (c + 2 < NC) {
            stage_load(Ah, Wh, sb + sl * STAGE_B, m0, n0, (c + 2) * 64, K, tid);
            CP_COMMIT();
            sl = (sl == 2) ? 0 : sl + 1;
        }
        stage_compute(sb + sc * STAGE_B, wm, wn, lane, acc);
        sc = (sc == 2) ? 0 : sc + 1;
    }

    const int gm = m0 + wm, gn = n0 + wn;
    const int r = lane >> 2, cp = (lane & 3) * 2;
#pragma unroll
    for (int mi = 0; mi < 2; mi++) {
#pragma unroll
        for (int nj = 0; nj < 8; nj++) {
            int row = gm + mi * 16 + r;
            int col = gn + nj * 8 + cp;
            float v0 = acc[mi][nj][0], v1 = acc[mi][nj][1];
            float v2 = acc[mi][nj][2], v3 = acc[mi][nj][3];
            if (OUT16) {
                if (second) {
                    float2 bb = *reinterpret_cast<const float2*>(&bias[col]);
                    v0 = dt_transform(v0, bb.x);
                    v1 = dt_transform(v1, bb.y);
                    v2 = dt_transform(v2, bb.x);
                    v3 = dt_transform(v3, bb.y);
                }
                ushort_t* C = second ? C2h : C1h;
                __half2 h01 = __halves2half2(__float2half(v0), __float2half(v1));
                __half2 h23 = __halves2half2(__float2half(v2), __float2half(v3));
                *reinterpret_cast<__half2*>(&C[(size_t)row * N + col]) = h01;
                *reinterpret_cast<__half2*>(&C[(size_t)(row + 8) * N + col]) = h23;
            } else {
                *reinterpret_cast<float2*>(&Cf[(size_t)row * N + col]) = make_float2(v0, v1);
                *reinterpret_cast<float2*>(&Cf[(size_t)(row + 8) * N + col]) = make_float2(v2, v3);
            }
        }
    }
}

__device__ __forceinline__ void bc_body(char* smem, int bid,
                                        const float* __restrict__ X,
                                        const float* __restrict__ WB,
                                        const float* __restrict__ WC) {
    float (*Xs)[65] = reinterpret_cast<float (*)[65]>(smem);
    float (*Ws)[65] = reinterpret_cast<float (*)[65]>(smem + 32 * 65 * sizeof(float));
    const int tid = threadIdx.x;
    const int tx = tid & 31;
    const int ty = tid >> 5;
    const int m0 = bid * 32;

    float acc[4];
#pragma unroll
    for (int i = 0; i < 4; i++) acc[i] = 0.0f;

    for (int kt = 0; kt < CDMODEL; kt += 64) {
#pragma unroll
        for (int j = 0; j < 2; j++) {
            int q = tid + j * 256;
            int row = q >> 4;
            int c4 = (q & 15) * 4;
            float4 v = *reinterpret_cast<const float4*>(&X[(size_t)(m0 + row) * CDMODEL + kt + c4]);
            Xs[row][c4 + 0] = v.x; Xs[row][c4 + 1] = v.y;
            Xs[row][c4 + 2] = v.z; Xs[row][c4 + 3] = v.w;
        }
#pragma unroll
        for (int j = 0; j < 2; j++) {
            int q = tid + j * 256;
            int row = q >> 4;
            int c4 = (q & 15) * 4;
            const float* Wsrc = (row < 16) ? &WB[(size_t)row * CDMODEL]
                                           : &WC[(size_t)(row - 16) * CDMODEL];
            float4 v = *reinterpret_cast<const float4*>(&Wsrc[kt + c4]);
            Ws[row][c4 + 0] = v.x; Ws[row][c4 + 1] = v.y;
            Ws[row][c4 + 2] = v.z; Ws[row][c4 + 3] = v.w;
        }
        __syncthreads();
#pragma unroll 8
        for (int k = 0; k < 64; k++) {
            float wv = Ws[tx][k];
#pragma unroll
            for (int i = 0; i < 4; i++)
                acc[i] = fmaf(Xs[ty * 4 + i][k], wv, acc[i]);
        }
        __syncthreads();
    }

#pragma unroll
    for (int i = 0; i < 4; i++) {
        float v = acc[i];
        float ss = v * v;
#pragma unroll
        for (int off = 8; off >= 1; off >>= 1)
            ss += __shfl_xor_sync(0xffffffffu, ss, off);
        float sc = 1.0f / fmaxf(sqrtf(ss), 1.0f);
        v *= sc;
        int m = m0 + ty * 4 + i;
        if (tx < 16) g_Bn[(size_t)m * 16 + tx] = v;
        else         g_Cn[(size_t)m * 16 + (tx - 16)] = v;
    }
}

__global__ __launch_bounds__(256, 2) void fused_front(
    const ushort_t* __restrict__ Ah,
    const ushort_t* __restrict__ W1, const ushort_t* __restrict__ W2,
    const float* __restrict__ bias,
    ushort_t* __restrict__ C1h, ushort_t* __restrict__ C2h,
    const float* __restrict__ X, const float* __restrict__ WB, const float* __restrict__ WC,
    const float* __restrict__ w3src, ushort_t* __restrict__ w3h) {
    extern __shared__ __align__(1024) char smem[];
    const int bx = blockIdx.x, by = blockIdx.y;

    if (bx < 32) {
        const bool second = (bx >= 16);
        const int n0 = (second ? bx - 16 : bx) * 128;
        const int m0 = by * 128;
        gemm_body<true>(smem, Ah, second ? W2 : W1, second, bias,
                        C1h, C2h, nullptr, m0, n0, CDMAMBA, CDMODEL);
    } else if (bx < 36) {
        bc_body(smem, (bx - 32) * 64 + by, X, WB, WC);
    } else {
        int id = ((bx - 36) * 64 + by) * 256 + threadIdx.x;
        conv_one(w3src, w3h, id);
    }
}

__global__ __launch_bounds__(256, 2) void gemm_out(
    const ushort_t* __restrict__ Ah, const ushort_t* __restrict__ Wh,
    float* __restrict__ Cf, int N, int K) {
    extern __shared__ __align__(1024) char smem[];
    gemm_body<false>(smem, Ah, Wh, false, nullptr, nullptr, nullptr, Cf,
                     blockIdx.y * 128, blockIdx.x * 128, N, K);
}

// ---------------- scan helpers ----------------
__device__ __forceinline__ bool check_fastA(const float* __restrict__ A_log, int d0) {
    int head = d0 / CHEADDIM;
    bool fast = true;
#pragma unroll
    for (int n = 0; n < 16; n++) {
        float a = expf(A_log[head * 16 + n]);
        if (fabsf(a - (float)(n + 1)) > 1e-3f * (float)(n + 1)) fast = false;
    }
    return fast;
}

__device__ __forceinline__ void load_Av(const float* __restrict__ A_log, int d, float* Av) {
    int head = d / CHEADDIM;
#pragma unroll
    for (int n = 0; n < 16; n++) Av[n] = expf(A_log[head * 16 + n]);
}

__device__ __forceinline__ void load16p(const float* p, ull_t* v) {
    const float4* q = reinterpret_cast<const float4*>(p);
    float4 a = q[0], b = q[1], c = q[2], d = q[3];
    v[0] = pk2(a.x, a.y); v[1] = pk2(a.z, a.w);
    v[2] = pk2(b.x, b.y); v[3] = pk2(b.z, b.w);
    v[4] = pk2(c.x, c.y); v[5] = pk2(c.z, c.w);
    v[6] = pk2(d.x, d.y); v[7] = pk2(d.z, d.w);
}

__device__ __forceinline__ void scan_step(ull_t* hp, const ull_t* Bp, float r, float dtx) {
    float r2 = r * r;
    ull_t p = pk2(r, r2);
    ull_t r22 = pk2(r2, r2);
    ull_t dtx2 = pk2(dtx, dtx);
#pragma unroll
    for (int k = 0; k < 8; k++) {
        if (k > 0) p = mul2(p, r22);
        hp[k] = fma2(p, hp[k], mul2(Bp[k], dtx2));
    }
}

__device__ __forceinline__ void scan_step_gen(ull_t* hp, const ull_t* Bp, const ull_t* Avp,
                                              float dt, float dtx) {
    ull_t dtx2 = pk2(dtx, dtx);
#pragma unroll
    for (int k = 0; k < 8; k++) {
        float a0, a1;
        upk2(Avp[k], a0, a1);
        ull_t dec = pk2(__expf(-dt * a0), __expf(-dt * a1));
        hp[k] = fma2(dec, hp[k], mul2(Bp[k], dtx2));
    }
}

// ---------------- scan pass 1: software-pipelined t-loop ----------------
__global__ __launch_bounds__(256) void scan_pass1(const float* __restrict__ A_log) {
    int i = blockIdx.x * 256 + threadIdx.x;
    int d0 = 2 * i;
    int c = blockIdx.y;
    int b = blockIdx.z;

    bool fastA = check_fastA(A_log, d0);
    ull_t Avp[8];
    if (!fastA) {
        float Av[16];
        load_Av(A_log, d0, Av);
#pragma unroll
        for (int k = 0; k < 8; k++) Avp[k] = pk2(Av[2 * k], Av[2 * k + 1]);
    }

    ull_t h0[8], h1[8];
    const ull_t z = pk2(0.0f, 0.0f);
#pragma unroll
    for (int k = 0; k < 8; k++) { h0[k] = z; h1[k] = z; }
    float S0 = 0.0f, S1 = 0.0f;

    int row0 = b * CSEQ + c * CLCHUNK;
    size_t ro = (size_t)row0 * CDMAMBA + d0;
    __half2 dtp = *reinterpret_cast<const __half2*>(&g_dt16[ro]);
    __half2 xp  = *reinterpret_cast<const __half2*>(&g_x16[ro]);
    ull_t Bp[8];
    load16p(g_Bn + (size_t)row0 * 16, Bp);

    for (int t = 0; t < CLCHUNK; t++) {
        __half2 dtn, xn;
        ull_t Bn[8];
        if (t + 1 < CLCHUNK) {
            size_t rn = (size_t)(row0 + t + 1) * CDMAMBA + d0;
            dtn = *reinterpret_cast<const __half2*>(&g_dt16[rn]);
            xn  = *reinterpret_cast<const __half2*>(&g_x16[rn]);
            load16p(g_Bn + (size_t)(row0 + t + 1) * 16, Bn);
        }
        float dt0 = __low2float(dtp), dt1 = __high2float(dtp);
        float x0 = __low2float(xp),   x1 = __high2float(xp);
        S0 += dt0; S1 += dt1;
        if (fastA) {
            scan_step(h0, Bp, __expf(-dt0), dt0 * x0);
            scan_step(h1, Bp, __expf(-dt1), dt1 * x1);
        } else {
            scan_step_gen(h0, Bp, Avp, dt0, dt0 * x0);
            scan_step_gen(h1, Bp, Avp, dt1, dt1 * x1);
        }
        if (t + 1 < CLCHUNK) {
            dtp = dtn; xp = xn;
#pragma unroll
            for (int k = 0; k < 8; k++) Bp[k] = Bn[k];
        }
    }
    size_t base = ((size_t)(b * CNCHUNK + c) * 16) * CDMAMBA + d0;
#pragma unroll
    for (int k = 0; k < 8; k++) {
        float a0, a1, b0, b1;
        upk2(h0[k], a0, a1);
        upk2(h1[k], b0, b1);
        *reinterpret_cast<float2*>(&g_hloc[base + (size_t)(2 * k) * CDMAMBA]) = make_float2(a0, b0);
        *reinterpret_cast<float2*>(&g_hloc[base + (size_t)(2 * k + 1) * CDMAMBA]) = make_float2(a1, b1);
    }
    *reinterpret_cast<float2*>(&g_S[(size_t)(b * CNCHUNK + c) * CDMAMBA + d0]) = make_float2(S0, S1);
}

// ---------------- scan pass 2 ----------------
__global__ __launch_bounds__(256) void scan_pass2(const float* __restrict__ A_log) {
    int idx = blockIdx.x * 256 + threadIdx.x;
    int d = idx % CDMAMBA;
    int bn = idx / CDMAMBA;
    int n = bn & 15;
    int b = bn >> 4;

    int head = d / CHEADDIM;
    float An = expf(A_log[head * 16 + n]);

    float h = 0.0f;
    for (int c = 0; c < CNCHUNK; c++) {
        size_t sidx = (size_t)(b * CNCHUNK + c) * CDMAMBA + d;
        size_t hidx = ((size_t)(b * CNCHUNK + c) * 16 + n) * CDMAMBA + d;
        g_hinit[hidx] = h;
        float S = g_S[sidx];
        h = fmaf(__expf(-S * An), h, g_hloc[hidx]);
    }
}

// ---------------- scan pass 3: software-pipelined, emit y fp16 ----------------
__global__ __launch_bounds__(256) void scan_pass3(const float* __restrict__ A_log,
                                                  const float* __restrict__ Dvec) {
    int i = blockIdx.x * 256 + threadIdx.x;
    int d0 = 2 * i;
    int c = blockIdx.y;
    int b = blockIdx.z;

    bool fastA = check_fastA(A_log, d0);
    ull_t Avp[8];
    if (!fastA) {
        float Av[16];
        load_Av(A_log, d0, Av);
#pragma unroll
        for (int k = 0; k < 8; k++) Avp[k] = pk2(Av[2 * k], Av[2 * k + 1]);
    }
    float2 Dd = *reinterpret_cast<const float2*>(&Dvec[d0]);

    ull_t h0[8], h1[8];
    size_t base = ((size_t)(b * CNCHUNK + c) * 16) * CDMAMBA + d0;
#pragma unroll
    for (int k = 0; k < 8; k++) {
        float2 va = *reinterpret_cast<const float2*>(&g_hinit[base + (size_t)(2 * k) * CDMAMBA]);
        float2 vb = *reinterpret_cast<const float2*>(&g_hinit[base + (size_t)(2 * k + 1) * CDMAMBA]);
        h0[k] = pk2(va.x, vb.x);
        h1[k] = pk2(va.y, vb.y);
    }

    int row0 = b * CSEQ + c * CLCHUNK;
    size_t ro = (size_t)row0 * CDMAMBA + d0;
    __half2 dtp = *reinterpret_cast<const __half2*>(&g_dt16[ro]);
    __half2 xp  = *reinterpret_cast<const __half2*>(&g_x16[ro]);
    ull_t Bp[8], Cp[8];
    load16p(g_Bn + (size_t)row0 * 16, Bp);
    load16p(g_Cn + (size_t)row0 * 16, Cp);

    for (int t = 0; t < CLCHUNK; t++) {
        __half2 dtn, xn;
        ull_t Bn[8], Cn[8];
        if (t + 1 < CLCHUNK) {
            size_t rn = (size_t)(row0 + t + 1) * CDMAMBA + d0;
            dtn = *reinterpret_cast<const __half2*>(&g_dt16[rn]);
            xn  = *reinterpret_cast<const __half2*>(&g_x16[rn]);
            load16p(g_Bn + (size_t)(row0 + t + 1) * 16, Bn);
            load16p(g_Cn + (size_t)(row0 + t + 1) * 16, Cn);
        }
        float dt0 = __low2float(dtp), dt1 = __high2float(dtp);
        float x0 = __low2float(xp),   x1 = __high2float(xp);
        if (fastA) {
            scan_step(h0, Bp, __expf(-dt0), dt0 * x0);
            scan_step(h1, Bp, __expf(-dt1), dt1 * x1);
        } else {
            scan_step_gen(h0, Bp, Avp, dt0, dt0 * x0);
            scan_step_gen(h1, Bp, Avp, dt1, dt1 * x1);
        }
        ull_t y0p = pk2(0.0f, 0.0f), y1p = pk2(0.0f, 0.0f);
#pragma unroll
        for (int k = 0; k < 8; k++) {
            y0p = fma2(h0[k], Cp[k], y0p);
            y1p = fma2(h1[k], Cp[k], y1p);
        }
        float ya, yb, yc, yd;
        upk2(y0p, ya, yb);
        upk2(y1p, yc, yd);
        float y0 = ya + yb, y1 = yc + yd;
        size_t rc = (size_t)(row0 + t) * CDMAMBA + d0;
        __half2 outv = __halves2half2(__float2half(fmaf(x0, Dd.x, y0)),
                                      __float2half(fmaf(x1, Dd.y, y1)));
        *reinterpret_cast<__half2*>(&g_y_h[rc]) = outv;
        if (t + 1 < CLCHUNK) {
            dtp = dtn; xp = xn;
#pragma unroll
            for (int k = 0; k < 8; k++) { Bp[k] = Bn[k]; Cp[k] = Cn[k]; }
        }
    }
}

// ---------------- launch ----------------
extern "C" void kernel_launch(void* const* d_in, const int* in_sizes, int n_in,
                              void* d_out, int out_size) {
    (void)in_sizes; (void)n_in; (void)out_size;
    const float* x_norm     = (const float*)d_in[0];
    const float* x_proj_w   = (const float*)d_in[1];
    const float* dt_proj_w  = (const float*)d_in[2];
    const float* dt_proj_b  = (const float*)d_in[3];
    const float* B_proj_w   = (const float*)d_in[4];
    const float* C_proj_w   = (const float*)d_in[5];
    const float* A_log      = (const float*)d_in[6];
    const float* Dvec       = (const float*)d_in[7];
    const float* out_proj_w = (const float*)d_in[8];
    float* out = (float*)d_out;

    void *p_xnh, *p_w1h, *p_w2h, *p_w3h, *p_yh, *p_x16, *p_dt16;
    cudaGetSymbolAddress(&p_xnh, g_xn_h);
    cudaGetSymbolAddress(&p_w1h, g_w1_h);
    cudaGetSymbolAddress(&p_w2h, g_w2_h);
    cudaGetSymbolAddress(&p_w3h, g_w3_h);
    cudaGetSymbolAddress(&p_yh, g_y_h);
    cudaGetSymbolAddress(&p_x16, g_x16);
    cudaGetSymbolAddress(&p_dt16, g_dt16);

    cudaFuncSetAttribute(fused_front, cudaFuncAttributeMaxDynamicSharedMemorySize, SM_TOTAL);
    cudaFuncSetAttribute(gemm_out, cudaFuncAttributeMaxDynamicSharedMemorySize, SM_TOTAL);

    // input conversions: xn, w1, w2
    {
        int total = (CMROWS * CDMODEL + 2 * CDMAMBA * CDMODEL) / 4;
        conv3<<<total / 256, 256>>>(x_norm, (ushort_t*)p_xnh,
                                    x_proj_w, (ushort_t*)p_w1h,
                                    dt_proj_w, (ushort_t*)p_w2h);
    }

    // fused front: GEMM1+2 + bc + conv_w3
    {
        dim3 grid(100, 64);
        fused_front<<<grid, 256, SM_TOTAL>>>(
            (const ushort_t*)p_xnh,
            (const ushort_t*)p_w1h, (const ushort_t*)p_w2h, dt_proj_b,
            (ushort_t*)p_x16, (ushort_t*)p_dt16,
            x_norm, B_proj_w, C_proj_w,
            out_proj_w, (ushort_t*)p_w3h);
    }

    // chunked selective scan
    dim3 scan_grid((CDMAMBA / 2) / 256, CNCHUNK, CBATCH);
    scan_pass1<<<scan_grid, 256>>>(A_log);
    scan_pass2<<<(CBATCH * 16 * CDMAMBA) / 256, 256>>>(A_log);
    scan_pass3<<<scan_grid, 256>>>(A_log, Dvec);

    // out = y @ out_proj_w^T (fp32)
    {
        dim3 grid(CDMAMBA / 128, CMROWS / 128);
        gemm_out<<<grid, 256, SM_TOTAL>>>(
            (const ushort_t*)p_yh, (const ushort_t*)p_w3h, out, CDMAMBA, CDMAMBA);
    }
}

// round 16
// speedup vs baseline: 1.0424x; 1.0418x over previous
#include <cuda_runtime.h>
#include <cuda_fp16.h>
#include <math.h>
#include <stdint.h>

#define CBATCH   4
#define CSEQ     2048
#define CDMODEL  1024
#define CDMAMBA  2048
#define CDSTATE  16
#define CNHEADS  32
#define CMROWS   (CBATCH * CSEQ)          // 8192
#define CNCHUNK  64
#define CLCHUNK  (CSEQ / CNCHUNK)         // 32
#define CHEADDIM (CDMAMBA / CNHEADS)      // 64

typedef unsigned short ushort_t;
typedef unsigned long long ull_t;

// ---------------- scratch ----------------
__device__ float g_Bn  [CMROWS * CDSTATE];
__device__ float g_Cn  [CMROWS * CDSTATE];
__device__ float g_hloc [CBATCH * CNCHUNK * CDSTATE * CDMAMBA];   // 32 MB
__device__ float g_hinit[CBATCH * CNCHUNK * CDSTATE * CDMAMBA];   // 32 MB
__device__ float g_S    [CBATCH * CNCHUNK * CDMAMBA];

__device__ ushort_t g_xn_h[CMROWS * CDMODEL];
__device__ ushort_t g_w1_h[CDMAMBA * CDMODEL];
__device__ ushort_t g_w2_h[CDMAMBA * CDMODEL];
__device__ ushort_t g_w3_h[CDMAMBA * CDMAMBA];
__device__ ushort_t g_x16 [CMROWS * CDMAMBA];
__device__ ushort_t g_dt16[CMROWS * CDMAMBA];
__device__ ushort_t g_y_h [CMROWS * CDMAMBA];

// ---------------- PTX helpers ----------------
__device__ __forceinline__ uint32_t smem_u32(const void* p) {
    uint32_t a;
    asm("{ .reg .u64 t; cvta.to.shared.u64 t, %1; cvt.u32.u64 %0, t; }" : "=r"(a) : "l"(p));
    return a;
}

#define CP_ASYNC16(dst, src) \
    asm volatile("cp.async.cg.shared.global [%0], [%1], 16;" :: "r"(dst), "l"(src))
#define CP_COMMIT() asm volatile("cp.async.commit_group;" ::: "memory")
#define CP_WAIT0() asm volatile("cp.async.wait_group 0;" ::: "memory")
#define CP_WAIT1() asm volatile("cp.async.wait_group 1;" ::: "memory")

#define LDSM4(r, addr) \
    asm volatile("ldmatrix.sync.aligned.m8n8.x4.shared.b16 {%0,%1,%2,%3}, [%4];" \
        : "=r"((r)[0]), "=r"((r)[1]), "=r"((r)[2]), "=r"((r)[3]) : "r"(addr))

#define MMA_F16(d, a, b0, b1) \
    asm volatile("mma.sync.aligned.m16n8k16.row.col.f32.f16.f16.f32 " \
        "{%0,%1,%2,%3}, {%4,%5,%6,%7}, {%8,%9}, {%0,%1,%2,%3};" \
        : "+f"((d)[0]), "+f"((d)[1]), "+f"((d)[2]), "+f"((d)[3]) \
        : "r"((a)[0]), "r"((a)[1]), "r"((a)[2]), "r"((a)[3]), "r"(b0), "r"(b1))

__device__ __forceinline__ uint32_t swz(uint32_t off) {
    return off ^ ((off >> 3) & 0x70);
}

__device__ __forceinline__ ull_t pk2(float lo, float hi) {
    ull_t r; asm("mov.b64 %0, {%1, %2};" : "=l"(r) : "f"(lo), "f"(hi)); return r;
}
__device__ __forceinline__ void upk2(ull_t v, float& lo, float& hi) {
    asm("mov.b64 {%0, %1}, %2;" : "=f"(lo), "=f"(hi) : "l"(v));
}
__device__ __forceinline__ ull_t mul2(ull_t a, ull_t b) {
    ull_t r; asm("mul.rn.f32x2 %0, %1, %2;" : "=l"(r) : "l"(a), "l"(b)); return r;
}
__device__ __forceinline__ ull_t fma2(ull_t a, ull_t b, ull_t c) {
    ull_t r; asm("fma.rn.f32x2 %0, %1, %2, %3;" : "=l"(r) : "l"(a), "l"(b), "l"(c)); return r;
}

// ---------------- conversions ----------------
__device__ __forceinline__ void conv_one(const float* __restrict__ in,
                                         ushort_t* __restrict__ hi, int i) {
    float4 v = reinterpret_cast<const float4*>(in)[i];
    ushort4 h;
    h.x = __half_as_ushort(__float2half(v.x));
    h.y = __half_as_ushort(__float2half(v.y));
    h.z = __half_as_ushort(__float2half(v.z));
    h.w = __half_as_ushort(__float2half(v.w));
    reinterpret_cast<ushort4*>(hi)[i] = h;
}

__global__ __launch_bounds__(256) void conv3(const float* __restrict__ xn, ushort_t* xh,
                                             const float* __restrict__ w1, ushort_t* w1h,
                                             const float* __restrict__ w2, ushort_t* w2h) {
    const int NA = (CMROWS * CDMODEL) / 4;
    const int NB = (CDMAMBA * CDMODEL) / 4;
    int id = blockIdx.x * 256 + threadIdx.x;
    if (id < NA)               conv_one(xn, xh, id);
    else if (id < NA + NB)     conv_one(w1, w1h, id - NA);
    else                       conv_one(w2, w2h, id - NA - NB);
}

__device__ __forceinline__ float dt_transform(float v, float b) {
    v += b;
    v = fminf(fmaxf(v, -10.0f), 5.0f);
    v = log1pf(expf(v));
    return fminf(fmaxf(v, 1e-4f), 0.1f);
}

// ---------------- GEMM building blocks (champion R8 geometry) ----------------
#define TILE_B   16384
#define STAGE_B  32768
#define SM_TOTAL (3 * STAGE_B)

__device__ __forceinline__ void stage_load(
    const ushort_t* __restrict__ Ah, const ushort_t* __restrict__ Wh,
    uint32_t sbase, int m0, int n0, int kc, int K, int tid) {
#pragma unroll
    for (int tile = 0; tile < 2; tile++) {
        const ushort_t* g = (tile == 0) ? Ah : Wh;
        int row0 = (tile == 0) ? m0 : n0;
#pragma unroll
        for (int j = 0; j < 4; j++) {
            int idx = tid + j * 256;
            int row = idx >> 3, seg = idx & 7;
            const ushort_t* src = g + (size_t)(row0 + row) * K + kc + seg * 8;
            uint32_t dst = sbase + tile * TILE_B + swz((uint32_t)(row * 128 + seg * 16));
            CP_ASYNC16(dst, src);
        }
    }
}

__device__ __forceinline__ void ldsm_frags(uint32_t aA, uint32_t aW,
                                           int arow, int akb, int brow, int bkb,
                                           int kb, uint32_t ah[2][4], uint32_t bh[4][4]) {
#pragma unroll
    for (int mi = 0; mi < 2; mi++) {
        uint32_t off = swz((uint32_t)((arow + mi * 16) * 128 + akb + kb));
        LDSM4(ah[mi], aA + off);
    }
#pragma unroll
    for (int ni = 0; ni < 4; ni++) {
        uint32_t off = swz((uint32_t)((brow + ni * 16) * 128 + bkb + kb));
        LDSM4(bh[ni], aW + off);
    }
}

__device__ __forceinline__ void stage_compute(uint32_t sbase, int wm, int wn,
                                              int lane, float acc[2][8][4]) {
    const uint32_t aA = sbase;
    const uint32_t aW = sbase + TILE_B;
    const int arow = wm + (lane & 15);
    const int akb  = (lane >> 4) * 16;
    const int brow = wn + ((lane >> 4) << 3) + (lane & 7);
    const int bkb  = ((lane >> 3) & 1) * 16;

    uint32_t ah[2][2][4], bh[2][4][4];
    ldsm_frags(aA, aW, arow, akb, brow, bkb, 0, ah[0], bh[0]);

#pragma unroll
    for (int ks = 0; ks < 4; ks++) {
        const int cur = ks & 1;
        if (ks < 3)
            ldsm_frags(aA, aW, arow, akb, brow, bkb, (ks + 1) * 32,
                       ah[cur ^ 1], bh[cur ^ 1]);
#pragma unroll
        for (int mi = 0; mi < 2; mi++) {
#pragma unroll
            for (int ni = 0; ni < 4; ni++) {
                MMA_F16(acc[mi][2 * ni + 0], ah[cur][mi], bh[cur][ni][0], bh[cur][ni][1]);
                MMA_F16(acc[mi][2 * ni + 1], ah[cur][mi], bh[cur][ni][2], bh[cur][ni][3]);
            }
        }
    }
}

template <bool OUT16>
__device__ __forceinline__ void gemm_body(
    char* smem, const ushort_t* __restrict__ Ah, const ushort_t* __restrict__ Wh,
    bool second, const float* __restrict__ bias,
    ushort_t* __restrict__ C1h, ushort_t* __restrict__ C2h, float* __restrict__ Cf,
    int m0, int n0, int N, int K) {
    const uint32_t sb = smem_u32(smem);
    const int tid = threadIdx.x, lane = tid & 31, w = tid >> 5;
    const int wm = (w & 3) * 32, wn = (w >> 2) * 64;
    const int NC = K >> 6;

    float acc[2][8][4];
#pragma unroll
    for (int i = 0; i < 2; i++)
#pragma unroll
        for (int j = 0; j < 8; j++)
#pragma unroll
            for (int q = 0; q < 4; q++) acc[i][j][q] = 0.0f;

    stage_load(Ah, Wh, sb + 0 * STAGE_B, m0, n0, 0, K, tid);  CP_COMMIT();
    stage_load(Ah, Wh, sb + 1 * STAGE_B, m0, n0, 64, K, tid); CP_COMMIT();

    int sc = 0, sl = 2;
    for (int c = 0; c < NC; c++) {
        if (c + 1 < NC) { CP_WAIT1(); } else { CP_WAIT0(); }
        __syncthreads();
        if (c + 2 < NC) {
            stage_load(Ah, Wh, sb + sl * STAGE_B, m0, n0, (c + 2) * 64, K, tid);
            CP_COMMIT();
            sl = (sl == 2) ? 0 : sl + 1;
        }
        stage_compute(sb + sc * STAGE_B, wm, wn, lane, acc);
        sc = (sc == 2) ? 0 : sc + 1;
    }

    const int gm = m0 + wm, gn = n0 + wn;
    const int r = lane >> 2, cp = (lane & 3) * 2;
#pragma unroll
    for (int mi = 0; mi < 2; mi++) {
#pragma unroll
        for (int nj = 0; nj < 8; nj++) {
            int row = gm + mi * 16 + r;
            int col = gn + nj * 8 + cp;
            float v0 = acc[mi][nj][0], v1 = acc[mi][nj][1];
            float v2 = acc[mi][nj][2], v3 = acc[mi][nj][3];
            if (OUT16) {
                if (second) {
                    float2 bb = *reinterpret_cast<const float2*>(&bias[col]);
                    v0 = dt_transform(v0, bb.x);
                    v1 = dt_transform(v1, bb.y);
                    v2 = dt_transform(v2, bb.x);
                    v3 = dt_transform(v3, bb.y);
                }
                ushort_t* C = second ? C2h : C1h;
                __half2 h01 = __halves2half2(__float2half(v0), __float2half(v1));
                __half2 h23 = __halves2half2(__float2half(v2), __float2half(v3));
                *reinterpret_cast<__half2*>(&C[(size_t)row * N + col]) = h01;
                *reinterpret_cast<__half2*>(&C[(size_t)(row + 8) * N + col]) = h23;
            } else {
                *reinterpret_cast<float2*>(&Cf[(size_t)row * N + col]) = make_float2(v0, v1);
                *reinterpret_cast<float2*>(&Cf[(size_t)(row + 8) * N + col]) = make_float2(v2, v3);
            }
        }
    }
}

__device__ __forceinline__ void bc_body(char* smem, int bid,
                                        const float* __restrict__ X,
                                        const float* __restrict__ WB,
                                        const float* __restrict__ WC) {
    float (*Xs)[65] = reinterpret_cast<float (*)[65]>(smem);
    float (*Ws)[65] = reinterpret_cast<float (*)[65]>(smem + 32 * 65 * sizeof(float));
    const int tid = threadIdx.x;
    const int tx = tid & 31;
    const int ty = tid >> 5;
    const int m0 = bid * 32;

    float acc[4];
#pragma unroll
    for (int i = 0; i < 4; i++) acc[i] = 0.0f;

    for (int kt = 0; kt < CDMODEL; kt += 64) {
#pragma unroll
        for (int j = 0; j < 2; j++) {
            int q = tid + j * 256;
            int row = q >> 4;
            int c4 = (q & 15) * 4;
            float4 v = *reinterpret_cast<const float4*>(&X[(size_t)(m0 + row) * CDMODEL + kt + c4]);
            Xs[row][c4 + 0] = v.x; Xs[row][c4 + 1] = v.y;
            Xs[row][c4 + 2] = v.z; Xs[row][c4 + 3] = v.w;
        }
#pragma unroll
        for (int j = 0; j < 2; j++) {
            int q = tid + j * 256;
            int row = q >> 4;
            int c4 = (q & 15) * 4;
            const float* Wsrc = (row < 16) ? &WB[(size_t)row * CDMODEL]
                                           : &WC[(size_t)(row - 16) * CDMODEL];
            float4 v = *reinterpret_cast<const float4*>(&Wsrc[kt + c4]);
            Ws[row][c4 + 0] = v.x; Ws[row][c4 + 1] = v.y;
            Ws[row][c4 + 2] = v.z; Ws[row][c4 + 3] = v.w;
        }
        __syncthreads();
#pragma unroll 8
        for (int k = 0; k < 64; k++) {
            float wv = Ws[tx][k];
#pragma unroll
            for (int i = 0; i < 4; i++)
                acc[i] = fmaf(Xs[ty * 4 + i][k], wv, acc[i]);
        }
        __syncthreads();
    }

#pragma unroll
    for (int i = 0; i < 4; i++) {
        float v = acc[i];
        float ss = v * v;
#pragma unroll
        for (int off = 8; off >= 1; off >>= 1)
            ss += __shfl_xor_sync(0xffffffffu, ss, off);
        float sc = 1.0f / fmaxf(sqrtf(ss), 1.0f);
        v *= sc;
        int m = m0 + ty * 4 + i;
        if (tx < 16) g_Bn[(size_t)m * 16 + tx] = v;
        else         g_Cn[(size_t)m * 16 + (tx - 16)] = v;
    }
}

__global__ __launch_bounds__(256, 2) void fused_front(
    const ushort_t* __restrict__ Ah,
    const ushort_t* __restrict__ W1, const ushort_t* __restrict__ W2,
    const float* __restrict__ bias,
    ushort_t* __restrict__ C1h, ushort_t* __restrict__ C2h,
    const float* __restrict__ X, const float* __restrict__ WB, const float* __restrict__ WC,
    const float* __restrict__ w3src, ushort_t* __restrict__ w3h) {
    extern __shared__ __align__(1024) char smem[];
    const int bx = blockIdx.x, by = blockIdx.y;

    if (bx < 32) {
        const bool second = (bx >= 16);
        const int n0 = (second ? bx - 16 : bx) * 128;
        const int m0 = by * 128;
        gemm_body<true>(smem, Ah, second ? W2 : W1, second, bias,
                        C1h, C2h, nullptr, m0, n0, CDMAMBA, CDMODEL);
    } else if (bx < 36) {
        bc_body(smem, (bx - 32) * 64 + by, X, WB, WC);
    } else {
        int id = ((bx - 36) * 64 + by) * 256 + threadIdx.x;
        conv_one(w3src, w3h, id);
    }
}

__global__ __launch_bounds__(256, 2) void gemm_out(
    const ushort_t* __restrict__ Ah, const ushort_t* __restrict__ Wh,
    float* __restrict__ Cf, int N, int K) {
    extern __shared__ __align__(1024) char smem[];
    gemm_body<false>(smem, Ah, Wh, false, nullptr, nullptr, nullptr, Cf,
                     blockIdx.y * 128, blockIdx.x * 128, N, K);
}

// ---------------- scan helpers ----------------
__device__ __forceinline__ bool check_fastA(const float* __restrict__ A_log, int d0) {
    int head = d0 / CHEADDIM;
    bool fast = true;
#pragma unroll
    for (int n = 0; n < 16; n++) {
        float a = expf(A_log[head * 16 + n]);
        if (fabsf(a - (float)(n + 1)) > 1e-3f * (float)(n + 1)) fast = false;
    }
    return fast;
}

__device__ __forceinline__ void load_Av(const float* __restrict__ A_log, int d, float* Av) {
    int head = d / CHEADDIM;
#pragma unroll
    for (int n = 0; n < 16; n++) Av[n] = expf(A_log[head * 16 + n]);
}

__device__ __forceinline__ void load16p(const float* p, ull_t* v) {
    const float4* q = reinterpret_cast<const float4*>(p);
    float4 a = q[0], b = q[1], c = q[2], d = q[3];
    v[0] = pk2(a.x, a.y); v[1] = pk2(a.z, a.w);
    v[2] = pk2(b.x, b.y); v[3] = pk2(b.z, b.w);
    v[4] = pk2(c.x, c.y); v[5] = pk2(c.z, c.w);
    v[6] = pk2(d.x, d.y); v[7] = pk2(d.z, d.w);
}

__device__ __forceinline__ void scan_step(ull_t* hp, const ull_t* Bp, float r, float dtx) {
    float r2 = r * r;
    ull_t p = pk2(r, r2);
    ull_t r22 = pk2(r2, r2);
    ull_t dtx2 = pk2(dtx, dtx);
#pragma unroll
    for (int k = 0; k < 8; k++) {
        if (k > 0) p = mul2(p, r22);
        hp[k] = fma2(p, hp[k], mul2(Bp[k], dtx2));
    }
}

__device__ __forceinline__ void scan_step_gen(ull_t* hp, const ull_t* Bp, const ull_t* Avp,
                                              float dt, float dtx) {
    ull_t dtx2 = pk2(dtx, dtx);
#pragma unroll
    for (int k = 0; k < 8; k++) {
        float a0, a1;
        upk2(Avp[k], a0, a1);
        ull_t dec = pk2(__expf(-dt * a0), __expf(-dt * a1));
        hp[k] = fma2(dec, hp[k], mul2(Bp[k], dtx2));
    }
}

// ---------------- scan pass 1: channels d0=2i, d1=2i+1 ----------------
__global__ __launch_bounds__(256) void scan_pass1(const float* __restrict__ A_log) {
    int i = blockIdx.x * 256 + threadIdx.x;
    int d0 = 2 * i;
    int c = blockIdx.y;
    int b = blockIdx.z;

    bool fastA = check_fastA(A_log, d0);
    ull_t Avp[8];
    if (!fastA) {
        float Av[16];
        load_Av(A_log, d0, Av);
#pragma unroll
        for (int k = 0; k < 8; k++) Avp[k] = pk2(Av[2 * k], Av[2 * k + 1]);
    }

    ull_t h0[8], h1[8];
    const ull_t z = pk2(0.0f, 0.0f);
#pragma unroll
    for (int k = 0; k < 8; k++) { h0[k] = z; h1[k] = z; }
    float S0 = 0.0f, S1 = 0.0f;

    int row0 = b * CSEQ + c * CLCHUNK;
    for (int t = 0; t < CLCHUNK; t++) {
        size_t ro = (size_t)(row0 + t) * CDMAMBA + d0;
        __half2 dtp = *reinterpret_cast<const __half2*>(&g_dt16[ro]);
        __half2 xp  = *reinterpret_cast<const __half2*>(&g_x16[ro]);
        float dt0 = __low2float(dtp), dt1 = __high2float(dtp);
        float x0 = __low2float(xp),   x1 = __high2float(xp);
        ull_t Bp[8];
        load16p(g_Bn + (size_t)(row0 + t) * 16, Bp);
        S0 += dt0; S1 += dt1;
        if (fastA) {
            scan_step(h0, Bp, __expf(-dt0), dt0 * x0);
            scan_step(h1, Bp, __expf(-dt1), dt1 * x1);
        } else {
            scan_step_gen(h0, Bp, Avp, dt0, dt0 * x0);
            scan_step_gen(h1, Bp, Avp, dt1, dt1 * x1);
        }
    }
    size_t base = ((size_t)(b * CNCHUNK + c) * 16) * CDMAMBA + d0;
#pragma unroll
    for (int k = 0; k < 8; k++) {
        float a0, a1, b0, b1;
        upk2(h0[k], a0, a1);
        upk2(h1[k], b0, b1);
        *reinterpret_cast<float2*>(&g_hloc[base + (size_t)(2 * k) * CDMAMBA]) = make_float2(a0, b0);
        *reinterpret_cast<float2*>(&g_hloc[base + (size_t)(2 * k + 1) * CDMAMBA]) = make_float2(a1, b1);
    }
    *reinterpret_cast<float2*>(&g_S[(size_t)(b * CNCHUNK + c) * CDMAMBA + d0]) = make_float2(S0, S1);
}

// ---------------- scan pass 2: one (b, n, d) chain per thread ----------------
__global__ __launch_bounds__(256) void scan_pass2(const float* __restrict__ A_log) {
    int idx = blockIdx.x * 256 + threadIdx.x;
    int d = idx % CDMAMBA;
    int bn = idx / CDMAMBA;
    int n = bn & 15;
    int b = bn >> 4;

    int head = d / CHEADDIM;
    float An = expf(A_log[head * 16 + n]);

    float h = 0.0f;
    for (int c = 0; c < CNCHUNK; c++) {
        size_t sidx = (size_t)(b * CNCHUNK + c) * CDMAMBA + d;
        size_t hidx = ((size_t)(b * CNCHUNK + c) * 16 + n) * CDMAMBA + d;
        g_hinit[hidx] = h;
        float S = g_S[sidx];
        h = fmaf(__expf(-S * An), h, g_hloc[hidx]);
    }
}

// ---------------- scan pass 3: emit y fp16 ----------------
__global__ __launch_bounds__(256) void scan_pass3(const float* __restrict__ A_log,
                                                  const float* __restrict__ Dvec) {
    int i = blockIdx.x * 256 + threadIdx.x;
    int d0 = 2 * i;
    int c = blockIdx.y;
    int b = blockIdx.z;

    bool fastA = check_fastA(A_log, d0);
    ull_t Avp[8];
    if (!fastA) {
        float Av[16];
        load_Av(A_log, d0, Av);
#pragma unroll
        for (int k = 0; k < 8; k++) Avp[k] = pk2(Av[2 * k], Av[2 * k + 1]);
    }
    float2 Dd = *reinterpret_cast<const float2*>(&Dvec[d0]);

    ull_t h0[8], h1[8];
    size_t base = ((size_t)(b * CNCHUNK + c) * 16) * CDMAMBA + d0;
#pragma unroll
    for (int k = 0; k < 8; k++) {
        float2 va = *reinterpret_cast<const float2*>(&g_hinit[base + (size_t)(2 * k) * CDMAMBA]);
        float2 vb = *reinterpret_cast<const float2*>(&g_hinit[base + (size_t)(2 * k + 1) * CDMAMBA]);
        h0[k] = pk2(va.x, vb.x);
        h1[k] = pk2(va.y, vb.y);
    }

    int row0 = b * CSEQ + c * CLCHUNK;
    for (int t = 0; t < CLCHUNK; t++) {
        size_t ro = (size_t)(row0 + t) * CDMAMBA + d0;
        __half2 dtp = *reinterpret_cast<const __half2*>(&g_dt16[ro]);
        __half2 xp  = *reinterpret_cast<const __half2*>(&g_x16[ro]);
        float dt0 = __low2float(dtp), dt1 = __high2float(dtp);
        float x0 = __low2float(xp),   x1 = __high2float(xp);
        ull_t Bp[8], Cp[8];
        load16p(g_Bn + (size_t)(row0 + t) * 16, Bp);
        load16p(g_Cn + (size_t)(row0 + t) * 16, Cp);
        if (fastA) {
            scan_step(h0, Bp, __expf(-dt0), dt0 * x0);
            scan_step(h1, Bp, __expf(-dt1), dt1 * x1);
        } else {
            scan_step_gen(h0, Bp, Avp, dt0, dt0 * x0);
            scan_step_gen(h1, Bp, Avp, dt1, dt1 * x1);
        }
        ull_t y0p = pk2(0.0f, 0.0f), y1p = pk2(0.0f, 0.0f);
#pragma unroll
        for (int k = 0; k < 8; k++) {
            y0p = fma2(h0[k], Cp[k], y0p);
            y1p = fma2(h1[k], Cp[k], y1p);
        }
        float ya, yb, yc, yd;
        upk2(y0p, ya, yb);
        upk2(y1p, yc, yd);
        float y0 = ya + yb, y1 = yc + yd;
        __half2 outv = __halves2half2(__float2half(fmaf(x0, Dd.x, y0)),
                                      __float2half(fmaf(x1, Dd.y, y1)));
        *reinterpret_cast<__half2*>(&g_y_h[ro]) = outv;
    }
}

// ---------------- launch ----------------
extern "C" void kernel_launch(void* const* d_in, const int* in_sizes, int n_in,
                              void* d_out, int out_size) {
    (void)in_sizes; (void)n_in; (void)out_size;
    const float* x_norm     = (const float*)d_in[0];
    const float* x_proj_w   = (const float*)d_in[1];
    const float* dt_proj_w  = (const float*)d_in[2];
    const float* dt_proj_b  = (const float*)d_in[3];
    const float* B_proj_w   = (const float*)d_in[4];
    const float* C_proj_w   = (const float*)d_in[5];
    const float* A_log      = (const float*)d_in[6];
    const float* Dvec       = (const float*)d_in[7];
    const float* out_proj_w = (const float*)d_in[8];
    float* out = (float*)d_out;

    void *p_xnh, *p_w1h, *p_w2h, *p_w3h, *p_yh, *p_x16, *p_dt16;
    cudaGetSymbolAddress(&p_xnh, g_xn_h);
    cudaGetSymbolAddress(&p_w1h, g_w1_h);
    cudaGetSymbolAddress(&p_w2h, g_w2_h);
    cudaGetSymbolAddress(&p_w3h, g_w3_h);
    cudaGetSymbolAddress(&p_yh, g_y_h);
    cudaGetSymbolAddress(&p_x16, g_x16);
    cudaGetSymbolAddress(&p_dt16, g_dt16);

    cudaFuncSetAttribute(fused_front, cudaFuncAttributeMaxDynamicSharedMemorySize, SM_TOTAL);
    cudaFuncSetAttribute(gemm_out, cudaFuncAttributeMaxDynamicSharedMemorySize, SM_TOTAL);

    // input conversions: xn, w1, w2
    {
        int total = (CMROWS * CDMODEL + 2 * CDMAMBA * CDMODEL) / 4;
        conv3<<<total / 256, 256>>>(x_norm, (ushort_t*)p_xnh,
                                    x_proj_w, (ushort_t*)p_w1h,
                                    dt_proj_w, (ushort_t*)p_w2h);
    }

    // fused front: GEMM1+2 + bc + conv_w3
    {
        dim3 grid(100, 64);
        fused_front<<<grid, 256, SM_TOTAL>>>(
            (const ushort_t*)p_xnh,
            (const ushort_t*)p_w1h, (const ushort_t*)p_w2h, dt_proj_b,
            (ushort_t*)p_x16, (ushort_t*)p_dt16,
            x_norm, B_proj_w, C_proj_w,
            out_proj_w, (ushort_t*)p_w3h);
    }

    // chunked selective scan (64 chunks of 32)
    dim3 scan_grid((CDMAMBA / 2) / 256, CNCHUNK, CBATCH);   // (4, 64, 4)
    scan_pass1<<<scan_grid, 256>>>(A_log);
    scan_pass2<<<(CBATCH * 16 * CDMAMBA) / 256, 256>>>(A_log);
    scan_pass3<<<scan_grid, 256>>>(A_log, Dvec);

    // out = y @ out_proj_w^T (fp32)
    {
        dim3 grid(CDMAMBA / 128, CMROWS / 128);
        gemm_out<<<grid, 256, SM_TOTAL>>>(
            (const ushort_t*)p_yh, (const ushort_t*)p_w3h, out, CDMAMBA, CDMAMBA);
    }
}

// round 17
// speedup vs baseline: 1.0899x; 1.0455x over previous
#include <cuda_runtime.h>
#include <cuda_fp16.h>
#include <math.h>
#include <stdint.h>

#define CBATCH   4
#define CSEQ     2048
#define CDMODEL  1024
#define CDMAMBA  2048
#define CDSTATE  16
#define CNHEADS  32
#define CMROWS   (CBATCH * CSEQ)          // 8192
#define CNCHUNK  32
#define CLCHUNK  (CSEQ / CNCHUNK)         // 64
#define CHEADDIM (CDMAMBA / CNHEADS)      // 64

typedef unsigned short ushort_t;
typedef unsigned long long ull_t;

// ---------------- scratch ----------------
__device__ float g_Bn  [CMROWS * CDSTATE];
__device__ float g_Cn  [CMROWS * CDSTATE];
__device__ float g_hloc [CBATCH * CNCHUNK * CDSTATE * CDMAMBA];
__device__ float g_hinit[CBATCH * CNCHUNK * CDSTATE * CDMAMBA];
__device__ float g_S    [CBATCH * CNCHUNK * CDMAMBA];

__device__ ushort_t g_xn_h[CMROWS * CDMODEL];
__device__ ushort_t g_w1_h[CDMAMBA * CDMODEL];
__device__ ushort_t g_w2_h[CDMAMBA * CDMODEL];
__device__ ushort_t g_w3_h[CDMAMBA * CDMAMBA];
__device__ ushort_t g_x16 [CMROWS * CDMAMBA];
__device__ ushort_t g_dt16[CMROWS * CDMAMBA];
__device__ ushort_t g_y_h [CMROWS * CDMAMBA];

// ---------------- PTX helpers ----------------
__device__ __forceinline__ uint32_t smem_u32(const void* p) {
    uint32_t a;
    asm("{ .reg .u64 t; cvta.to.shared.u64 t, %1; cvt.u32.u64 %0, t; }" : "=r"(a) : "l"(p));
    return a;
}

#define CP_ASYNC16(dst, src) \
    asm volatile("cp.async.cg.shared.global [%0], [%1], 16;" :: "r"(dst), "l"(src))
#define CP_COMMIT() asm volatile("cp.async.commit_group;" ::: "memory")
#define CP_WAIT0() asm volatile("cp.async.wait_group 0;" ::: "memory")
#define CP_WAIT1() asm volatile("cp.async.wait_group 1;" ::: "memory")

#define LDSM4(r, addr) \
    asm volatile("ldmatrix.sync.aligned.m8n8.x4.shared.b16 {%0,%1,%2,%3}, [%4];" \
        : "=r"((r)[0]), "=r"((r)[1]), "=r"((r)[2]), "=r"((r)[3]) : "r"(addr))

#define MMA_F16(d, a, b0, b1) \
    asm volatile("mma.sync.aligned.m16n8k16.row.col.f32.f16.f16.f32 " \
        "{%0,%1,%2,%3}, {%4,%5,%6,%7}, {%8,%9}, {%0,%1,%2,%3};" \
        : "+f"((d)[0]), "+f"((d)[1]), "+f"((d)[2]), "+f"((d)[3]) \
        : "r"((a)[0]), "r"((a)[1]), "r"((a)[2]), "r"((a)[3]), "r"(b0), "r"(b1))

__device__ __forceinline__ uint32_t swz(uint32_t off) {
    return off ^ ((off >> 3) & 0x70);
}

__device__ __forceinline__ ull_t pk2(float lo, float hi) {
    ull_t r; asm("mov.b64 %0, {%1, %2};" : "=l"(r) : "f"(lo), "f"(hi)); return r;
}
__device__ __forceinline__ void upk2(ull_t v, float& lo, float& hi) {
    asm("mov.b64 {%0, %1}, %2;" : "=f"(lo), "=f"(hi) : "l"(v));
}
__device__ __forceinline__ ull_t mul2(ull_t a, ull_t b) {
    ull_t r; asm("mul.rn.f32x2 %0, %1, %2;" : "=l"(r) : "l"(a), "l"(b)); return r;
}
__device__ __forceinline__ ull_t fma2(ull_t a, ull_t b, ull_t c) {
    ull_t r; asm("fma.rn.f32x2 %0, %1, %2, %3;" : "=l"(r) : "l"(a), "l"(b), "l"(c)); return r;
}

// ---------------- conversions ----------------
__device__ __forceinline__ void conv_one(const float* __restrict__ in,
                                         ushort_t* __restrict__ hi, int i) {
    float4 v = reinterpret_cast<const float4*>(in)[i];
    ushort4 h;
    h.x = __half_as_ushort(__float2half(v.x));
    h.y = __half_as_ushort(__float2half(v.y));
    h.z = __half_as_ushort(__float2half(v.z));
    h.w = __half_as_ushort(__float2half(v.w));
    reinterpret_cast<ushort4*>(hi)[i] = h;
}

__global__ __launch_bounds__(256) void conv3(const float* __restrict__ xn, ushort_t* xh,
                                             const float* __restrict__ w1, ushort_t* w1h,
                                             const float* __restrict__ w2, ushort_t* w2h) {
    const int NA = (CMROWS * CDMODEL) / 4;
    const int NB = (CDMAMBA * CDMODEL) / 4;
    int id = blockIdx.x * 256 + threadIdx.x;
    if (id < NA)               conv_one(xn, xh, id);
    else if (id < NA + NB)     conv_one(w1, w1h, id - NA);
    else                       conv_one(w2, w2h, id - NA - NB);
}

__device__ __forceinline__ float dt_transform(float v, float b) {
    v += b;
    v = fminf(fmaxf(v, -10.0f), 5.0f);
    v = log1pf(expf(v));
    return fminf(fmaxf(v, 1e-4f), 0.1f);
}

// ---------------- GEMM building blocks (champion R8 geometry) ----------------
#define TILE_B   16384
#define STAGE_B  32768
#define SM_TOTAL (3 * STAGE_B)

__device__ __forceinline__ void stage_load(
    const ushort_t* __restrict__ Ah, const ushort_t* __restrict__ Wh,
    uint32_t sbase, int m0, int n0, int kc, int K, int tid) {
#pragma unroll
    for (int tile = 0; tile < 2; tile++) {
        const ushort_t* g = (tile == 0) ? Ah : Wh;
        int row0 = (tile == 0) ? m0 : n0;
#pragma unroll
        for (int j = 0; j < 4; j++) {
            int idx = tid + j * 256;
            int row = idx >> 3, seg = idx & 7;
            const ushort_t* src = g + (size_t)(row0 + row) * K + kc + seg * 8;
            uint32_t dst = sbase + tile * TILE_B + swz((uint32_t)(row * 128 + seg * 16));
            CP_ASYNC16(dst, src);
        }
    }
}

__device__ __forceinline__ void ldsm_frags(uint32_t aA, uint32_t aW,
                                           int arow, int akb, int brow, int bkb,
                                           int kb, uint32_t ah[2][4], uint32_t bh[4][4]) {
#pragma unroll
    for (int mi = 0; mi < 2; mi++) {
        uint32_t off = swz((uint32_t)((arow + mi * 16) * 128 + akb + kb));
        LDSM4(ah[mi], aA + off);
    }
#pragma unroll
    for (int ni = 0; ni < 4; ni++) {
        uint32_t off = swz((uint32_t)((brow + ni * 16) * 128 + bkb + kb));
        LDSM4(bh[ni], aW + off);
    }
}

__device__ __forceinline__ void stage_compute(uint32_t sbase, int wm, int wn,
                                              int lane, float acc[2][8][4]) {
    const uint32_t aA = sbase;
    const uint32_t aW = sbase + TILE_B;
    const int arow = wm + (lane & 15);
    const int akb  = (lane >> 4) * 16;
    const int brow = wn + ((lane >> 4) << 3) + (lane & 7);
    const int bkb  = ((lane >> 3) & 1) * 16;

    uint32_t ah[2][2][4], bh[2][4][4];
    ldsm_frags(aA, aW, arow, akb, brow, bkb, 0, ah[0], bh[0]);

#pragma unroll
    for (int ks = 0; ks < 4; ks++) {
        const int cur = ks & 1;
        if (ks < 3)
            ldsm_frags(aA, aW, arow, akb, brow, bkb, (ks + 1) * 32,
                       ah[cur ^ 1], bh[cur ^ 1]);
#pragma unroll
        for (int mi = 0; mi < 2; mi++) {
#pragma unroll
            for (int ni = 0; ni < 4; ni++) {
                MMA_F16(acc[mi][2 * ni + 0], ah[cur][mi], bh[cur][ni][0], bh[cur][ni][1]);
                MMA_F16(acc[mi][2 * ni + 1], ah[cur][mi], bh[cur][ni][2], bh[cur][ni][3]);
            }
        }
    }
}

template <bool OUT16>
__device__ __forceinline__ void gemm_body(
    char* smem, const ushort_t* __restrict__ Ah, const ushort_t* __restrict__ Wh,
    bool second, const float* __restrict__ bias,
    ushort_t* __restrict__ C1h, ushort_t* __restrict__ C2h, float* __restrict__ Cf,
    int m0, int n0, int N, int K) {
    const uint32_t sb = smem_u32(smem);
    const int tid = threadIdx.x, lane = tid & 31, w = tid >> 5;
    const int wm = (w & 3) * 32, wn = (w >> 2) * 64;
    const int NC = K >> 6;

    float acc[2][8][4];
#pragma unroll
    for (int i = 0; i < 2; i++)
#pragma unroll
        for (int j = 0; j < 8; j++)
#pragma unroll
            for (int q = 0; q < 4; q++) acc[i][j][q] = 0.0f;

    stage_load(Ah, Wh, sb + 0 * STAGE_B, m0, n0, 0, K, tid);  CP_COMMIT();
    stage_load(Ah, Wh, sb + 1 * STAGE_B, m0, n0, 64, K, tid); CP_COMMIT();

    int sc = 0, sl = 2;
    for (int c = 0; c < NC; c++) {
        if (c + 1 < NC) { CP_WAIT1(); } else { CP_WAIT0(); }
        __syncthreads();
        if (c + 2 < NC) {
            stage_load(Ah, Wh, sb + sl * STAGE_B, m0, n0, (c + 2) * 64, K, tid);
            CP_COMMIT();
            sl = (sl == 2) ? 0 : sl + 1;
        }
        stage_compute(sb + sc * STAGE_B, wm, wn, lane, acc);
        sc = (sc == 2) ? 0 : sc + 1;
    }

    const int gm = m0 + wm, gn = n0 + wn;
    const int r = lane >> 2, cp = (lane & 3) * 2;
#pragma unroll
    for (int mi = 0; mi < 2; mi++) {
#pragma unroll
        for (int nj = 0; nj < 8; nj++) {
            int row = gm + mi * 16 + r;
            int col = gn + nj * 8 + cp;
            float v0 = acc[mi][nj][0], v1 = acc[mi][nj][1];
            float v2 = acc[mi][nj][2], v3 = acc[mi][nj][3];
            if (OUT16) {
                if (second) {
                    float2 bb = *reinterpret_cast<const float2*>(&bias[col]);
                    v0 = dt_transform(v0, bb.x);
                    v1 = dt_transform(v1, bb.y);
                    v2 = dt_transform(v2, bb.x);
                    v3 = dt_transform(v3, bb.y);
                }
                ushort_t* C = second ? C2h : C1h;
                __half2 h01 = __halves2half2(__float2half(v0), __float2half(v1));
                __half2 h23 = __halves2half2(__float2half(v2), __float2half(v3));
                *reinterpret_cast<__half2*>(&C[(size_t)row * N + col]) = h01;
                *reinterpret_cast<__half2*>(&C[(size_t)(row + 8) * N + col]) = h23;
            } else {
                *reinterpret_cast<float2*>(&Cf[(size_t)row * N + col]) = make_float2(v0, v1);
                *reinterpret_cast<float2*>(&Cf[(size_t)(row + 8) * N + col]) = make_float2(v2, v3);
            }
        }
    }
}

__device__ __forceinline__ void bc_body(char* smem, int bid,
                                        const float* __restrict__ X,
                                        const float* __restrict__ WB,
                                        const float* __restrict__ WC) {
    float (*Xs)[65] = reinterpret_cast<float (*)[65]>(smem);
    float (*Ws)[65] = reinterpret_cast<float (*)[65]>(smem + 32 * 65 * sizeof(float));
    const int tid = threadIdx.x;
    const int tx = tid & 31;
    const int ty = tid >> 5;
    const int m0 = bid * 32;

    float acc[4];
#pragma unroll
    for (int i = 0; i < 4; i++) acc[i] = 0.0f;

    for (int kt = 0; kt < CDMODEL; kt += 64) {
#pragma unroll
        for (int j = 0; j < 2; j++) {
            int q = tid + j * 256;
            int row = q >> 4;
            int c4 = (q & 15) * 4;
            float4 v = *reinterpret_cast<const float4*>(&X[(size_t)(m0 + row) * CDMODEL + kt + c4]);
            Xs[row][c4 + 0] = v.x; Xs[row][c4 + 1] = v.y;
            Xs[row][c4 + 2] = v.z; Xs[row][c4 + 3] = v.w;
        }
#pragma unroll
        for (int j = 0; j < 2; j++) {
            int q = tid + j * 256;
            int row = q >> 4;
            int c4 = (q & 15) * 4;
            const float* Wsrc = (row < 16) ? &WB[(size_t)row * CDMODEL]
                                           : &WC[(size_t)(row - 16) * CDMODEL];
            float4 v = *reinterpret_cast<const float4*>(&Wsrc[kt + c4]);
            Ws[row][c4 + 0] = v.x; Ws[row][c4 + 1] = v.y;
            Ws[row][c4 + 2] = v.z; Ws[row][c4 + 3] = v.w;
        }
        __syncthreads();
#pragma unroll 8
        for (int k = 0; k < 64; k++) {
            float wv = Ws[tx][k];
#pragma unroll
            for (int i = 0; i < 4; i++)
                acc[i] = fmaf(Xs[ty * 4 + i][k], wv, acc[i]);
        }
        __syncthreads();
    }

#pragma unroll
    for (int i = 0; i < 4; i++) {
        float v = acc[i];
        float ss = v * v;
#pragma unroll
        for (int off = 8; off >= 1; off >>= 1)
            ss += __shfl_xor_sync(0xffffffffu, ss, off);
        float sc = 1.0f / fmaxf(sqrtf(ss), 1.0f);
        v *= sc;
        int m = m0 + ty * 4 + i;
        if (tx < 16) g_Bn[(size_t)m * 16 + tx] = v;
        else         g_Cn[(size_t)m * 16 + (tx - 16)] = v;
    }
}

// ---------------- FUSED FRONT: GEMM1+2 (bx<32) + bc (32<=bx<36) + conv_w3 (36<=bx<52)
// grid (52, 64), 256 threads, dynamic smem 96KB. conv_w3: 4 quanta/thread.
__global__ __launch_bounds__(256, 2) void fused_front(
    const ushort_t* __restrict__ Ah,
    const ushort_t* __restrict__ W1, const ushort_t* __restrict__ W2,
    const float* __restrict__ bias,
    ushort_t* __restrict__ C1h, ushort_t* __restrict__ C2h,
    const float* __restrict__ X, const float* __restrict__ WB, const float* __restrict__ WC,
    const float* __restrict__ w3src, ushort_t* __restrict__ w3h) {
    extern __shared__ __align__(1024) char smem[];
    const int bx = blockIdx.x, by = blockIdx.y;

    if (bx < 32) {
        const bool second = (bx >= 16);
        const int n0 = (second ? bx - 16 : bx) * 128;
        const int m0 = by * 128;
        gemm_body<true>(smem, Ah, second ? W2 : W1, second, bias,
                        C1h, C2h, nullptr, m0, n0, CDMAMBA, CDMODEL);
    } else if (bx < 36) {
        bc_body(smem, (bx - 32) * 64 + by, X, WB, WC);
    } else {
        int base = (((bx - 36) * 64 + by) * 256 + threadIdx.x) * 4;  // 4 quanta/thread
#pragma unroll
        for (int j = 0; j < 4; j++) conv_one(w3src, w3h, base + j);
    }
}

__global__ __launch_bounds__(256, 2) void gemm_out(
    const ushort_t* __restrict__ Ah, const ushort_t* __restrict__ Wh,
    float* __restrict__ Cf, int N, int K) {
    extern __shared__ __align__(1024) char smem[];
    gemm_body<false>(smem, Ah, Wh, false, nullptr, nullptr, nullptr, Cf,
                     blockIdx.y * 128, blockIdx.x * 128, N, K);
}

// ---------------- scan helpers ----------------
__device__ __forceinline__ bool check_fastA(const float* __restrict__ A_log, int d0) {
    int head = d0 / CHEADDIM;
    bool fast = true;
#pragma unroll
    for (int n = 0; n < 16; n++) {
        float a = expf(A_log[head * 16 + n]);
        if (fabsf(a - (float)(n + 1)) > 1e-3f * (float)(n + 1)) fast = false;
    }
    return fast;
}

__device__ __forceinline__ void load_Av(const float* __restrict__ A_log, int d, float* Av) {
    int head = d / CHEADDIM;
#pragma unroll
    for (int n = 0; n < 16; n++) Av[n] = expf(A_log[head * 16 + n]);
}

__device__ __forceinline__ void load16p(const float* p, ull_t* v) {
    const float4* q = reinterpret_cast<const float4*>(p);
    float4 a = q[0], b = q[1], c = q[2], d = q[3];
    v[0] = pk2(a.x, a.y); v[1] = pk2(a.z, a.w);
    v[2] = pk2(b.x, b.y); v[3] = pk2(b.z, b.w);
    v[4] = pk2(c.x, c.y); v[5] = pk2(c.z, c.w);
    v[6] = pk2(d.x, d.y); v[7] = pk2(d.z, d.w);
}

__device__ __forceinline__ void scan_step(ull_t* hp, const ull_t* Bp, float r, float dtx) {
    float r2 = r * r;
    ull_t p = pk2(r, r2);
    ull_t r22 = pk2(r2, r2);
    ull_t dtx2 = pk2(dtx, dtx);
#pragma unroll
    for (int k = 0; k < 8; k++) {
        if (k > 0) p = mul2(p, r22);
        hp[k] = fma2(p, hp[k], mul2(Bp[k], dtx2));
    }
}

__device__ __forceinline__ void scan_step_gen(ull_t* hp, const ull_t* Bp, const ull_t* Avp,
                                              float dt, float dtx) {
    ull_t dtx2 = pk2(dtx, dtx);
#pragma unroll
    for (int k = 0; k < 8; k++) {
        float a0, a1;
        upk2(Avp[k], a0, a1);
        ull_t dec = pk2(__expf(-dt * a0), __expf(-dt * a1));
        hp[k] = fma2(dec, hp[k], mul2(Bp[k], dtx2));
    }
}

// ---------------- scan pass 1: channels d0=2i, d1=2i+1 ----------------
__global__ __launch_bounds__(256) void scan_pass1(const float* __restrict__ A_log) {
    int i = blockIdx.x * 256 + threadIdx.x;
    int d0 = 2 * i;
    int c = blockIdx.y;
    int b = blockIdx.z;

    bool fastA = check_fastA(A_log, d0);
    ull_t Avp[8];
    if (!fastA) {
        float Av[16];
        load_Av(A_log, d0, Av);
#pragma unroll
        for (int k = 0; k < 8; k++) Avp[k] = pk2(Av[2 * k], Av[2 * k + 1]);
    }

    ull_t h0[8], h1[8];
    const ull_t z = pk2(0.0f, 0.0f);
#pragma unroll
    for (int k = 0; k < 8; k++) { h0[k] = z; h1[k] = z; }
    float S0 = 0.0f, S1 = 0.0f;

    int row0 = b * CSEQ + c * CLCHUNK;
    for (int t = 0; t < CLCHUNK; t++) {
        size_t ro = (size_t)(row0 + t) * CDMAMBA + d0;
        __half2 dtp = *reinterpret_cast<const __half2*>(&g_dt16[ro]);
        __half2 xp  = *reinterpret_cast<const __half2*>(&g_x16[ro]);
        float dt0 = __low2float(dtp), dt1 = __high2float(dtp);
        float x0 = __low2float(xp),   x1 = __high2float(xp);
        ull_t Bp[8];
        load16p(g_Bn + (size_t)(row0 + t) * 16, Bp);
        S0 += dt0; S1 += dt1;
        if (fastA) {
            scan_step(h0, Bp, __expf(-dt0), dt0 * x0);
            scan_step(h1, Bp, __expf(-dt1), dt1 * x1);
        } else {
            scan_step_gen(h0, Bp, Avp, dt0, dt0 * x0);
            scan_step_gen(h1, Bp, Avp, dt1, dt1 * x1);
        }
    }
    size_t base = ((size_t)(b * CNCHUNK + c) * 16) * CDMAMBA + d0;
#pragma unroll
    for (int k = 0; k < 8; k++) {
        float a0, a1, b0, b1;
        upk2(h0[k], a0, a1);
        upk2(h1[k], b0, b1);
        *reinterpret_cast<float2*>(&g_hloc[base + (size_t)(2 * k) * CDMAMBA]) = make_float2(a0, b0);
        *reinterpret_cast<float2*>(&g_hloc[base + (size_t)(2 * k + 1) * CDMAMBA]) = make_float2(a1, b1);
    }
    *reinterpret_cast<float2*>(&g_S[(size_t)(b * CNCHUNK + c) * CDMAMBA + d0]) = make_float2(S0, S1);
}

// ---------------- scan pass 2: one (b, n, d) chain per thread ----------------
__global__ __launch_bounds__(256) void scan_pass2(const float* __restrict__ A_log) {
    int idx = blockIdx.x * 256 + threadIdx.x;
    int d = idx % CDMAMBA;
    int bn = idx / CDMAMBA;
    int n = bn & 15;
    int b = bn >> 4;

    int head = d / CHEADDIM;
    float An = expf(A_log[head * 16 + n]);

    float h = 0.0f;
    for (int c = 0; c < CNCHUNK; c++) {
        size_t sidx = (size_t)(b * CNCHUNK + c) * CDMAMBA + d;
        size_t hidx = ((size_t)(b * CNCHUNK + c) * 16 + n) * CDMAMBA + d;
        g_hinit[hidx] = h;
        float S = g_S[sidx];
        h = fmaf(__expf(-S * An), h, g_hloc[hidx]);
    }
}

// ---------------- scan pass 3: emit y fp16 ----------------
__global__ __launch_bounds__(256) void scan_pass3(const float* __restrict__ A_log,
                                                  const float* __restrict__ Dvec) {
    int i = blockIdx.x * 256 + threadIdx.x;
    int d0 = 2 * i;
    int c = blockIdx.y;
    int b = blockIdx.z;

    bool fastA = check_fastA(A_log, d0);
    ull_t Avp[8];
    if (!fastA) {
        float Av[16];
        load_Av(A_log, d0, Av);
#pragma unroll
        for (int k = 0; k < 8; k++) Avp[k] = pk2(Av[2 * k], Av[2 * k + 1]);
    }
    float2 Dd = *reinterpret_cast<const float2*>(&Dvec[d0]);

    ull_t h0[8], h1[8];
    size_t base = ((size_t)(b * CNCHUNK + c) * 16) * CDMAMBA + d0;
#pragma unroll
    for (int k = 0; k < 8; k++) {
        float2 va = *reinterpret_cast<const float2*>(&g_hinit[base + (size_t)(2 * k) * CDMAMBA]);
        float2 vb = *reinterpret_cast<const float2*>(&g_hinit[base + (size_t)(2 * k + 1) * CDMAMBA]);
        h0[k] = pk2(va.x, vb.x);
        h1[k] = pk2(va.y, vb.y);
    }

    int row0 = b * CSEQ + c * CLCHUNK;
    for (int t = 0; t < CLCHUNK; t++) {
        size_t ro = (size_t)(row0 + t) * CDMAMBA + d0;
        __half2 dtp = *reinterpret_cast<const __half2*>(&g_dt16[ro]);
        __half2 xp  = *reinterpret_cast<const __half2*>(&g_x16[ro]);
        float dt0 = __low2float(dtp), dt1 = __high2float(dtp);
        float x0 = __low2float(xp),   x1 = __high2float(xp);
        ull_t Bp[8], Cp[8];
        load16p(g_Bn + (size_t)(row0 + t) * 16, Bp);
        load16p(g_Cn + (size_t)(row0 + t) * 16, Cp);
        if (fastA) {
            scan_step(h0, Bp, __expf(-dt0), dt0 * x0);
            scan_step(h1, Bp, __expf(-dt1), dt1 * x1);
        } else {
            scan_step_gen(h0, Bp, Avp, dt0, dt0 * x0);
            scan_step_gen(h1, Bp, Avp, dt1, dt1 * x1);
        }
        ull_t y0p = pk2(0.0f, 0.0f), y1p = pk2(0.0f, 0.0f);
#pragma unroll
        for (int k = 0; k < 8; k++) {
            y0p = fma2(h0[k], Cp[k], y0p);
            y1p = fma2(h1[k], Cp[k], y1p);
        }
        float ya, yb, yc, yd;
        upk2(y0p, ya, yb);
        upk2(y1p, yc, yd);
        float y0 = ya + yb, y1 = yc + yd;
        __half2 outv = __halves2half2(__float2half(fmaf(x0, Dd.x, y0)),
                                      __float2half(fmaf(x1, Dd.y, y1)));
        *reinterpret_cast<__half2*>(&g_y_h[ro]) = outv;
    }
}

// ---------------- launch ----------------
extern "C" void kernel_launch(void* const* d_in, const int* in_sizes, int n_in,
                              void* d_out, int out_size) {
    (void)in_sizes; (void)n_in; (void)out_size;
    const float* x_norm     = (const float*)d_in[0];
    const float* x_proj_w   = (const float*)d_in[1];
    const float* dt_proj_w  = (const float*)d_in[2];
    const float* dt_proj_b  = (const float*)d_in[3];
    const float* B_proj_w   = (const float*)d_in[4];
    const float* C_proj_w   = (const float*)d_in[5];
    const float* A_log      = (const float*)d_in[6];
    const float* Dvec       = (const float*)d_in[7];
    const float* out_proj_w = (const float*)d_in[8];
    float* out = (float*)d_out;

    void *p_xnh, *p_w1h, *p_w2h, *p_w3h, *p_yh, *p_x16, *p_dt16;
    cudaGetSymbolAddress(&p_xnh, g_xn_h);
    cudaGetSymbolAddress(&p_w1h, g_w1_h);
    cudaGetSymbolAddress(&p_w2h, g_w2_h);
    cudaGetSymbolAddress(&p_w3h, g_w3_h);
    cudaGetSymbolAddress(&p_yh, g_y_h);
    cudaGetSymbolAddress(&p_x16, g_x16);
    cudaGetSymbolAddress(&p_dt16, g_dt16);

    cudaFuncSetAttribute(fused_front, cudaFuncAttributeMaxDynamicSharedMemorySize, SM_TOTAL);
    cudaFuncSetAttribute(gemm_out, cudaFuncAttributeMaxDynamicSharedMemorySize, SM_TOTAL);

    // input conversions: xn, w1, w2
    {
        int total = (CMROWS * CDMODEL + 2 * CDMAMBA * CDMODEL) / 4;
        conv3<<<total / 256, 256>>>(x_norm, (ushort_t*)p_xnh,
                                    x_proj_w, (ushort_t*)p_w1h,
                                    dt_proj_w, (ushort_t*)p_w2h);
    }

    // fused front: GEMM1+2 + bc + conv_w3 (coarsened)
    {
        dim3 grid(52, 64);
        fused_front<<<grid, 256, SM_TOTAL>>>(
            (const ushort_t*)p_xnh,
            (const ushort_t*)p_w1h, (const ushort_t*)p_w2h, dt_proj_b,
            (ushort_t*)p_x16, (ushort_t*)p_dt16,
            x_norm, B_proj_w, C_proj_w,
            out_proj_w, (ushort_t*)p_w3h);
    }

    // chunked selective scan (32 chunks of 64 — champion config)
    dim3 scan_grid((CDMAMBA / 2) / 256, CNCHUNK, CBATCH);   // (4, 32, 4)
    scan_pass1<<<scan_grid, 256>>>(A_log);
    scan_pass2<<<(CBATCH * 16 * CDMAMBA) / 256, 256>>>(A_log);
    scan_pass3<<<scan_grid, 256>>>(A_log, Dvec);

    // out = y @ out_proj_w^T (fp32)
    {
        dim3 grid(CDMAMBA / 128, CMROWS / 128);
        gemm_out<<<grid, 256, SM_TOTAL>>>(
            (const ushort_t*)p_yh, (const ushort_t*)p_w3h, out, CDMAMBA, CDMAMBA);
    }
}